// round 15
// baseline (speedup 1.0000x reference)
#include <cuda_runtime.h>
#include <cuda_fp16.h>
#include <cstdint>
#include <math.h>

// ---------------- problem constants ----------------
#define BB 64
#define CC 512
#define SS 512
#define EE 257
#define MTOT (BB*CC)                 // 32768
#define KP  256                      // low-plane row stride (e<256 only)
#define PSL ((size_t)MTOT*KP)
#define NWP 1024                     // proj N = 4*256 (interleaved col = 4e+p)
#define XW  512                      // packed X row stride / irfft K
#define PS  ((size_t)BB*CC*CC)

#define INV_SQRT_S 0.04419417382415922f
#define TWO_PI_OVER_S 0.01227184630308513f
#define ATTN_SCALE 0.06237828615518053f   // 1/sqrt(257)

// ---------------- scratch (static device globals) ----------------
__device__ __align__(256) float g_bias[NWP];
__device__ __align__(256) float g_Wny[4*SS];
__device__ __align__(256) float g_ny[4*MTOT];
__device__ __align__(256) float g_S[6*PS];
__device__ __align__(256) float g_Xny[MTOT];
__device__ __align__(256) __half g_xh[(size_t)MTOT*SS];
__device__ __align__(256) __half g_xl[(size_t)MTOT*SS];
__device__ __align__(256) __half g_WTh[NWP*SS];
__device__ __align__(256) __half g_WTl[NWP*SS];
__device__ __align__(256) __half g_CT[SS*XW];
__device__ __align__(256) __half g_lowh[6*PSL];
__device__ __align__(256) __half g_lowl[6*PSL];
__device__ __align__(256) __half g_P[(size_t)MTOT*1024];
__device__ __align__(256) __half g_vt[(size_t)BB*2*256*1024];
__device__ __align__(256) __half g_X[(size_t)MTOT*XW];

// ---------------- helpers ----------------
__device__ __forceinline__ uint32_t smem_u32(const void* p) {
    uint32_t a;
    asm("{ .reg .u64 t; cvta.to.shared.u64 t, %1; cvt.u32.u64 %0, t; }" : "=r"(a) : "l"(p));
    return a;
}
__device__ __forceinline__ void hsplit(float v, __half* h, __half* l) {
    __half a = __float2half_rn(v);
    *h = a;
    *l = __float2half_rn(v - __half2float(a));
}
__device__ __forceinline__ void ldsm4(uint32_t (&r)[4], uint32_t a) {
    asm volatile("ldmatrix.sync.aligned.m8n8.x4.shared.b16 {%0,%1,%2,%3}, [%4];"
                 : "=r"(r[0]), "=r"(r[1]), "=r"(r[2]), "=r"(r[3]) : "r"(a));
}
__device__ __forceinline__ void mma16816b(float (&d)[4], const uint32_t (&a)[4],
                                          uint32_t b0, uint32_t b1) {
    asm volatile(
        "mma.sync.aligned.m16n8k16.row.col.f32.f16.f16.f32 "
        "{%0,%1,%2,%3},{%4,%5,%6,%7},{%8,%9},{%0,%1,%2,%3};"
        : "+f"(d[0]), "+f"(d[1]), "+f"(d[2]), "+f"(d[3])
        : "r"(a[0]), "r"(a[1]), "r"(a[2]), "r"(a[3]), "r"(b0), "r"(b1));
}
__device__ __forceinline__ void cpasync16(uint32_t s, const void* g) {
    asm volatile("cp.async.cg.shared.global [%0], [%1], 16;" :: "r"(s), "l"(g));
}
__device__ __forceinline__ void wait_upto(int n) {
    if (n >= 2)      asm volatile("cp.async.wait_group 2;");
    else if (n == 1) asm volatile("cp.async.wait_group 1;");
    else             asm volatile("cp.async.wait_group 0;");
}
__device__ __forceinline__ float plane256(int pn, int r) {
    if (pn == 4) return g_ny[0 * MTOT + r] + g_ny[1 * MTOT + r];
    if (pn == 5) return g_ny[2 * MTOT + r] + g_ny[3 * MTOT + r];
    return g_ny[pn * MTOT + r];
}

// ---------------- builder kernels ----------------

// WT interleaved: row index n = 4*e + p (e<256); e=256 column -> g_Wny
__global__ void build_w_kernel(const float* __restrict__ l1r, const float* __restrict__ l1i,
                               const float* __restrict__ h1r, const float* __restrict__ h1i)
{
    __shared__ float cr[257], ci[257];
    int s = blockIdx.x;
    for (int k = threadIdx.x; k < 257; k += blockDim.x) {
        int idx = (s * k) & 511;
        float ang = (float)idx * TWO_PI_OVER_S;
        float sn, cs;
        sincosf(ang, &sn, &cs);
        cr[k] = cs * INV_SQRT_S;
        ci[k] = -sn * INV_SQRT_S;
    }
    __syncthreads();
    for (int e = threadIdx.x; e < EE; e += blockDim.x) {
        float wlr = 0.f, wli = 0.f, whr = 0.f, whi = 0.f;
        for (int k = 0; k < 128; k++) {
            float ar = cr[k], ai = ci[k];
            float br = l1r[k * EE + e], bi = l1i[k * EE + e];
            wlr += ar * br - ai * bi;
            wli += ar * bi + ai * br;
        }
        for (int k = 0; k < 129; k++) {
            float ar = cr[128 + k], ai = ci[128 + k];
            float br = h1r[k * EE + e], bi = h1i[k * EE + e];
            whr += ar * br - ai * bi;
            whi += ar * bi + ai * br;
        }
        if (e < 256) {
            hsplit(wlr, &g_WTh[(4 * e + 0) * SS + s], &g_WTl[(4 * e + 0) * SS + s]);
            hsplit(wli, &g_WTh[(4 * e + 1) * SS + s], &g_WTl[(4 * e + 1) * SS + s]);
            hsplit(whr, &g_WTh[(4 * e + 2) * SS + s], &g_WTl[(4 * e + 2) * SS + s]);
            hsplit(whi, &g_WTh[(4 * e + 3) * SS + s], &g_WTl[(4 * e + 3) * SS + s]);
        } else {
            g_Wny[0 * SS + s] = wlr;
            g_Wny[1 * SS + s] = wli;
            g_Wny[2 * SS + s] = whr;
            g_Wny[3 * SS + s] = whi;
        }
    }
}

__global__ void build_bias_kernel(const float* __restrict__ lbr, const float* __restrict__ lbi,
                                  const float* __restrict__ hbr, const float* __restrict__ hbi)
{
    int n = blockIdx.x * blockDim.x + threadIdx.x;
    if (n >= NWP) return;
    int p = n & 3, e = n >> 2;
    const float* src = (p == 0) ? lbr : (p == 1) ? lbi : (p == 2) ? hbr : hbi;
    g_bias[n] = src[e];
}

__global__ void splitx_ny_kernel(const float* __restrict__ x,
                                 const float* __restrict__ lbr, const float* __restrict__ lbi,
                                 const float* __restrict__ hbr, const float* __restrict__ hbi)
{
    __shared__ float sW[4][512];
    __shared__ float sb[4];
    int t = threadIdx.x;
    for (int i = t; i < 4 * 512; i += 256) sW[i >> 9][i & 511] = g_Wny[i];
    if (t == 0) { sb[0] = lbr[256]; sb[1] = lbi[256]; sb[2] = hbr[256]; sb[3] = hbi[256]; }
    __syncthreads();
    int warp = t >> 5, lane = t & 31;
    int row = blockIdx.x * 8 + warp;
    const float* xr = x + (size_t)row * SS;
    float a0 = 0.f, a1 = 0.f, a2 = 0.f, a3 = 0.f;
#pragma unroll
    for (int i = 0; i < 4; i++) {
        int s = i * 128 + lane * 4;
        float4 v = *(const float4*)(xr + s);
        float vv[4] = {v.x, v.y, v.z, v.w};
        __half hh[4], ll[4];
#pragma unroll
        for (int j = 0; j < 4; j++) {
            hsplit(vv[j], &hh[j], &ll[j]);
            a0 += vv[j] * sW[0][s + j];
            a1 += vv[j] * sW[1][s + j];
            a2 += vv[j] * sW[2][s + j];
            a3 += vv[j] * sW[3][s + j];
        }
        size_t d = (size_t)row * SS + s;
        *(__half2*)&g_xh[d]     = __halves2half2(hh[0], hh[1]);
        *(__half2*)&g_xh[d + 2] = __halves2half2(hh[2], hh[3]);
        *(__half2*)&g_xl[d]     = __halves2half2(ll[0], ll[1]);
        *(__half2*)&g_xl[d + 2] = __halves2half2(ll[2], ll[3]);
    }
#pragma unroll
    for (int o = 16; o; o >>= 1) {
        a0 += __shfl_xor_sync(0xffffffffu, a0, o);
        a1 += __shfl_xor_sync(0xffffffffu, a1, o);
        a2 += __shfl_xor_sync(0xffffffffu, a2, o);
        a3 += __shfl_xor_sync(0xffffffffu, a3, o);
    }
    if (lane == 0) {
        g_ny[0 * MTOT + row] = fmaxf(a0 + sb[0], 0.f);
        g_ny[1 * MTOT + row] = fmaxf(a1 + sb[1], 0.f);
        g_ny[2 * MTOT + row] = fmaxf(a2 + sb[2], 0.f);
        g_ny[3 * MTOT + row] = fmaxf(a3 + sb[3], 0.f);
    }
}

__global__ void build_ct_kernel()
{
    int idx = blockIdx.x * blockDim.x + threadIdx.x;
    if (idx >= SS * XW) return;
    int s = idx / XW, k = idx - s * XW;
    float v;
    if (k < 256) {
        int e = k;
        float w = (e == 0) ? 1.f : 2.f;
        float ang = (float)((e * s) & 511) * TWO_PI_OVER_S;
        v = w * cosf(ang) * INV_SQRT_S;
    } else {
        int e = k - 256;
        if (e == 0) v = 0.f;
        else {
            float ang = (float)((e * s) & 511) * TWO_PI_OVER_S;
            v = -2.f * sinf(ang) * INV_SQRT_S;
        }
    }
    g_CT[idx] = __float2half_rn(v);
}

__global__ void vt_kernel()
{
    __shared__ float tr[32][33], ti[32][33];
    int b = blockIdx.z, e0 = blockIdx.y * 32, c0 = blockIdx.x * 32;
    int tx = threadIdx.x, ty = threadIdx.y;
    for (int r = ty; r < 32; r += 8) {
        size_t src = ((size_t)(b * CC + c0 + r)) * KP + (e0 + tx);
        tr[r][tx] = __half2float(g_lowh[0 * PSL + src]) + __half2float(g_lowl[0 * PSL + src]);
        ti[r][tx] = __half2float(g_lowh[1 * PSL + src]) + __half2float(g_lowl[1 * PSL + src]);
    }
    __syncthreads();
    for (int r = ty; r < 32; r += 8) {
        int n = e0 + r, c = c0 + tx;
        float lr = tr[tx][r], li = ti[tx][r];
        size_t d0 = ((size_t)(b * 2 + 0) * 256 + n) * 1024;
        size_t d1 = ((size_t)(b * 2 + 1) * 256 + n) * 1024;
        g_vt[d0 + c]       = __float2half_rn(lr);
        g_vt[d0 + 512 + c] = __float2half_rn(-li);
        g_vt[d1 + c]       = __float2half_rn(li);
        g_vt[d1 + 512 + c] = __float2half_rn(lr);
    }
}

// ============ FUSED 3-product engine: 256x128 tile, 512 threads ============
// K-chunk 32, 4 stages x 48KB, prefetch depth 3, wait_group 2.

struct GF {
    const __half *Ah, *Al, *Bh, *Bl;
    int lda, ldb, nkc;
};

#define FSTG 49152u

__device__ __forceinline__ void gloadF(const GF& g, int kc, int stg, uint32_t base, int t)
{
    uint32_t sb = base + (uint32_t)stg * FSTG;
    int rA = t >> 1, cA2 = (t & 1) * 2;
    const __half* gAh = g.Ah + (size_t)rA * g.lda + kc * 32 + cA2 * 8;
    const __half* gAl = g.Al + (size_t)rA * g.lda + kc * 32 + cA2 * 8;
    uint32_t mA = (uint32_t)((rA >> 1) & 3);
    uint32_t sAh = sb + (uint32_t)rA * 64u;
    uint32_t sAl = sAh + 16384u;
#pragma unroll
    for (int i = 0; i < 2; i++) {
        uint32_t c = (uint32_t)(cA2 + i);
        uint32_t sw = (c ^ mA) << 4;
        cpasync16(sAh + sw, gAh + i * 8);
        cpasync16(sAl + sw, gAl + i * 8);
    }
    int rB = t >> 2, cB = t & 3;
    const __half* gBh = g.Bh + (size_t)rB * g.ldb + kc * 32 + cB * 8;
    const __half* gBl = g.Bl + (size_t)rB * g.ldb + kc * 32 + cB * 8;
    uint32_t swB = (uint32_t)((cB ^ ((rB >> 1) & 3)) << 4);
    uint32_t sBh = sb + 32768u + (uint32_t)rB * 64u;
    uint32_t sBl = sBh + 8192u;
    cpasync16(sBh + swB, gBh);
    cpasync16(sBl + swB, gBl);
    asm volatile("cp.async.commit_group;");
}

__device__ __forceinline__ void gemmF_run(const GF& g, float (&acc)[4][4][4], uint32_t base)
{
    const int t = threadIdx.x;
    const int warp = t >> 5, lane = t & 31;
    const int wr = warp >> 2, wc = warp & 3;
    const int nkc = g.nkc;

    gloadF(g, 0, 0, base, t);
    if (nkc > 1) gloadF(g, 1, 1, base, t);
    if (nkc > 2) gloadF(g, 2, 2, base, t);
    for (int ch = 0; ch < nkc; ch++) {
        wait_upto(nkc - 1 - ch);
        __syncthreads();
        if (ch + 3 < nkc) gloadF(g, ch + 3, (ch + 3) & 3, base, t);
        uint32_t sb = base + (uint32_t)(ch & 3) * FSTG;
        uint32_t sAh = sb, sAl = sb + 16384u, sBh = sb + 32768u, sBl = sb + 40960u;
#pragma unroll
        for (int s = 0; s < 2; s++) {
            uint32_t aoffv[4], boffv[2];
#pragma unroll
            for (int mt = 0; mt < 4; mt++) {
                int row = wr * 64 + mt * 16 + (lane & 15);
                uint32_t u = (uint32_t)(s * 2 + (lane >> 4));
                aoffv[mt] = (uint32_t)row * 64u + (((u ^ ((uint32_t)(row >> 1) & 3u))) << 4);
            }
#pragma unroll
            for (int ntp = 0; ntp < 2; ntp++) {
                int row = wc * 32 + ntp * 16 + (((lane >> 4) & 1) << 3) + (lane & 7);
                uint32_t u = (uint32_t)(s * 2 + ((lane >> 3) & 1));
                boffv[ntp] = (uint32_t)row * 64u + (((u ^ ((uint32_t)(row >> 1) & 3u))) << 4);
            }
            uint32_t a[4][4], bh[2][4], bl[2][4];
#pragma unroll
            for (int mt = 0; mt < 4; mt++) ldsm4(a[mt], sAh + aoffv[mt]);
#pragma unroll
            for (int ntp = 0; ntp < 2; ntp++) {
                ldsm4(bh[ntp], sBh + boffv[ntp]);
                ldsm4(bl[ntp], sBl + boffv[ntp]);
            }
#pragma unroll
            for (int mt = 0; mt < 4; mt++)
#pragma unroll
                for (int nt = 0; nt < 4; nt++)
                    mma16816b(acc[mt][nt], a[mt], bh[nt >> 1][(nt & 1) * 2],
                              bh[nt >> 1][(nt & 1) * 2 + 1]);
#pragma unroll
            for (int mt = 0; mt < 4; mt++)
#pragma unroll
                for (int nt = 0; nt < 4; nt++)
                    mma16816b(acc[mt][nt], a[mt], bl[nt >> 1][(nt & 1) * 2],
                              bl[nt >> 1][(nt & 1) * 2 + 1]);
#pragma unroll
            for (int mt = 0; mt < 4; mt++) ldsm4(a[mt], sAl + aoffv[mt]);
#pragma unroll
            for (int mt = 0; mt < 4; mt++)
#pragma unroll
                for (int nt = 0; nt < 4; nt++)
                    mma16816b(acc[mt][nt], a[mt], bh[nt >> 1][(nt & 1) * 2],
                              bh[nt >> 1][(nt & 1) * 2 + 1]);
        }
    }
    __syncthreads();
}

#define MMA_SMEMF (4 * FSTG + 128)

// ============ single-product 256x128 engine, 512 threads, 4 stages ============

struct GS {
    const __half *A, *B;
    int lda, ldb, nkc;
};

#define SSTG 49152u

__device__ __forceinline__ void gloadS(const GS& g, int kc, int stg, uint32_t base, int t)
{
    uint32_t sb = base + (uint32_t)stg * SSTG;
    int rA = t >> 1, cA = (t & 1) * 4;
    const __half* gA = g.A + (size_t)rA * g.lda + kc * 64 + cA * 8;
    uint32_t sA = sb + (uint32_t)rA * 128u;
#pragma unroll
    for (int i = 0; i < 4; i++) {
        int c = cA + i;
        uint32_t sw = (uint32_t)((c ^ (rA & 7)) << 4);
        cpasync16(sA + sw, gA + i * 8);
    }
    int rB = t >> 2, cB = (t & 3) * 2;
    const __half* gB = g.B + (size_t)rB * g.ldb + kc * 64 + cB * 8;
    uint32_t sB = sb + 32768u + (uint32_t)rB * 128u;
#pragma unroll
    for (int i = 0; i < 2; i++) {
        int c = cB + i;
        uint32_t sw = (uint32_t)((c ^ (rB & 7)) << 4);
        cpasync16(sB + sw, gB + i * 8);
    }
    asm volatile("cp.async.commit_group;");
}

__device__ __forceinline__ void gemmS_run(const GS& g, float (&acc)[4][4][4], uint32_t base)
{
    const int t = threadIdx.x;
    const int warp = t >> 5, lane = t & 31;
    const int wr = warp >> 2, wc = warp & 3;
    const int nkc = g.nkc;

    gloadS(g, 0, 0, base, t);
    if (nkc > 1) gloadS(g, 1, 1, base, t);
    if (nkc > 2) gloadS(g, 2, 2, base, t);
    for (int ch = 0; ch < nkc; ch++) {
        wait_upto(nkc - 1 - ch);
        __syncthreads();
        if (ch + 3 < nkc) gloadS(g, ch + 3, (ch + 3) & 3, base, t);
        uint32_t sb = base + (uint32_t)(ch & 3) * SSTG;
        uint32_t sA = sb, sB = sb + 32768u;
#pragma unroll
        for (int s = 0; s < 4; s++) {
            uint32_t a[4][4], b[2][4];
#pragma unroll
            for (int mt = 0; mt < 4; mt++) {
                int row = wr * 64 + mt * 16 + (lane & 15);
                int u = s * 2 + (lane >> 4);
                ldsm4(a[mt], sA + (uint32_t)row * 128u + (uint32_t)((u ^ (row & 7)) << 4));
            }
#pragma unroll
            for (int ntp = 0; ntp < 2; ntp++) {
                int row = wc * 32 + ntp * 16 + (((lane >> 4) & 1) << 3) + (lane & 7);
                int u = s * 2 + ((lane >> 3) & 1);
                ldsm4(b[ntp], sB + (uint32_t)row * 128u + (uint32_t)((u ^ (row & 7)) << 4));
            }
#pragma unroll
            for (int mt = 0; mt < 4; mt++)
#pragma unroll
                for (int nt = 0; nt < 4; nt++)
                    mma16816b(acc[mt][nt], a[mt], b[nt >> 1][(nt & 1) * 2],
                              b[nt >> 1][(nt & 1) * 2 + 1]);
        }
    }
    __syncthreads();
}

#define MMA_SMEMS (4 * SSTG + 128)

#define GEMM_PRE() \
    extern __shared__ char dynsm[]; \
    uint32_t raw = smem_u32(dynsm); \
    uint32_t base = (raw + 127u) & ~127u; \
    char* smp = dynsm + (base - raw); \
    (void)smp; \
    float acc[4][4][4]; \
    for (int i = 0; i < 4; i++) for (int j = 0; j < 4; j++) for (int q = 0; q < 4; q++) acc[i][j][q] = 0.f; \
    const int warp = threadIdx.x >> 5, lane = threadIdx.x & 31; \
    const int wr = warp >> 2, wc = warp & 3; \
    const int gr = lane >> 2, gc = lane & 3;

// ---------------- proj: relu(x@W + bias), fused 256x128, interleaved N ----------------
// col = 4e+p; each thread's acc pair is (plane p, plane p+1) of the SAME e,
// so sum planes (ls, hs) are computed in-register -> sum_kernel eliminated.
__global__ __launch_bounds__(512, 1) void proj_mma()
{
    GEMM_PRE();
    int n0 = blockIdx.x * 128, m0 = blockIdx.y * 256;
    GF g;
    g.Ah = g_xh + (size_t)m0 * SS;   g.Al = g_xl + (size_t)m0 * SS;
    g.Bh = g_WTh + (size_t)n0 * SS;  g.Bl = g_WTl + (size_t)n0 * SS;
    g.lda = SS; g.ldb = SS; g.nkc = 16;
    gemmF_run(g, acc, base);
#pragma unroll
    for (int mt = 0; mt < 4; mt++) {
#pragma unroll
        for (int nt = 0; nt < 4; nt++) {
            int col = n0 + wc * 32 + nt * 8 + gc * 2;
            int e = col >> 2, p = col & 3;          // p in {0, 2}
            int sp = 4 + (p >> 1);                  // sum plane: 4 (low) or 5 (high)
            float b0 = g_bias[col], b1 = g_bias[col + 1];
#pragma unroll
            for (int h = 0; h < 2; h++) {
                int row = m0 + wr * 64 + mt * 16 + gr + h * 8;
                float v0 = fmaxf(acc[mt][nt][h * 2 + 0] + b0, 0.f);
                float v1 = fmaxf(acc[mt][nt][h * 2 + 1] + b1, 0.f);
                size_t dbase = (size_t)row * KP + e;
                hsplit(v0, &g_lowh[(size_t)p * PSL + dbase],
                           &g_lowl[(size_t)p * PSL + dbase]);
                hsplit(v1, &g_lowh[(size_t)(p + 1) * PSL + dbase],
                           &g_lowl[(size_t)(p + 1) * PSL + dbase]);
                hsplit(v0 + v1, &g_lowh[(size_t)sp * PSL + dbase],
                                &g_lowl[(size_t)sp * PSL + dbase]);
            }
        }
    }
}

// ---------------- score: 6 Karatsuba planes, fused, symmetric-skip + rank-1 ----------------
// Symmetric planes: tiles (0, n_t in {2,3}) also write their transpose through smem,
// replacing the mirror kernel.
__global__ __launch_bounds__(512, 1) void score_mma()
{
    int z = blockIdx.z;
    int b = z / 6, which = z - b * 6;
    int hi = (which >= 3) ? 1 : 0;
    int w = which - 3 * hi;
    int apn = (w == 2) ? 4 : w;
    int bpn = hi ? ((w == 2) ? 5 : w + 2) : apn;
    int m_t, n_t;
    bool dotrans = false;
    if (!hi) {
        int tid8 = blockIdx.y * 4 + blockIdx.x;
        if (tid8 >= 6) return;
        const int mts[6] = {0, 0, 0, 0, 1, 1};
        const int nts[6] = {0, 1, 2, 3, 2, 3};
        m_t = mts[tid8]; n_t = nts[tid8];
        dotrans = (tid8 == 2 || tid8 == 3);
    } else {
        m_t = blockIdx.y; n_t = blockIdx.x;
    }
    GEMM_PRE();
    __shared__ float sA256[256], sB256[128];
    int m0 = m_t * 256, n0 = n_t * 128;
    if (threadIdx.x < 256)
        sA256[threadIdx.x] = plane256(apn, b * CC + m0 + threadIdx.x);
    else if (threadIdx.x < 384)
        sB256[threadIdx.x - 256] = plane256(bpn, b * CC + n0 + threadIdx.x - 256);
    size_t aoff = (size_t)apn * PSL + (size_t)(b * CC + m0) * KP;
    size_t boff = (size_t)bpn * PSL + (size_t)(b * CC + n0) * KP;
    GF g;
    g.Ah = g_lowh + aoff;  g.Al = g_lowl + aoff;
    g.Bh = g_lowh + boff;  g.Bl = g_lowl + boff;
    g.lda = KP; g.ldb = KP; g.nkc = 8;
    gemmF_run(g, acc, base);
    float* out = g_S + (size_t)which * PS + (size_t)(b * CC) * CC;
#pragma unroll
    for (int mt = 0; mt < 4; mt++) {
#pragma unroll
        for (int nt = 0; nt < 4; nt++) {
            int cl = wc * 32 + nt * 8 + gc * 2;
            float bv0 = sB256[cl], bv1 = sB256[cl + 1];
            int col = n0 + cl;
#pragma unroll
            for (int h = 0; h < 2; h++) {
                int rl = wr * 64 + mt * 16 + gr + h * 8;
                float av = sA256[rl];
                int row = m0 + rl;
                *(float2*)&out[(size_t)row * CC + col] =
                    make_float2(acc[mt][nt][h * 2 + 0] + av * bv0,
                                acc[mt][nt][h * 2 + 1] + av * bv1);
            }
        }
    }
    if (dotrans) {
        // write transpose of this tile: target rows n0..n0+127, cols 0..255 (m0 == 0)
        float* T = (float*)smp;   // [128][132]
        for (int h2 = 0; h2 < 2; h2++) {
            __syncthreads();
            if ((wr >> 1) == h2) {
#pragma unroll
                for (int mt = 0; mt < 4; mt++) {
#pragma unroll
                    for (int nt = 0; nt < 4; nt++) {
                        int cl = wc * 32 + nt * 8 + gc * 2;
                        float bv0 = sB256[cl], bv1 = sB256[cl + 1];
#pragma unroll
                        for (int h = 0; h < 2; h++) {
                            int rl = wr * 64 + mt * 16 + gr + h * 8;
                            int j = rl - h2 * 128;
                            float av = sA256[rl];
                            T[cl * 132 + j]       = acc[mt][nt][h * 2 + 0] + av * bv0;
                            T[(cl + 1) * 132 + j] = acc[mt][nt][h * 2 + 1] + av * bv1;
                        }
                    }
                }
            }
            __syncthreads();
            for (int idx = threadIdx.x; idx < 128 * 32; idx += 512) {
                int c = idx >> 5, q = idx & 31;
                float4 v = *(float4*)&T[c * 132 + q * 4];
                *(float4*)&out[(size_t)(n0 + c) * CC + (h2 * 128 + q * 4)] = v;
            }
        }
    }
}

// ---------------- softmax + Karatsuba combine -> P fp16 [Pr|Pi]; also xr[256] ----------------
__device__ __forceinline__ void softmax16(float (&v)[16])
{
    float m = -3.4e38f;
#pragma unroll
    for (int u = 0; u < 16; u++) m = fmaxf(m, v[u]);
#pragma unroll
    for (int o = 16; o; o >>= 1) m = fmaxf(m, __shfl_xor_sync(0xffffffffu, m, o));
    float s = 0.f;
#pragma unroll
    for (int u = 0; u < 16; u++) { v[u] = expf(v[u] - m); s += v[u]; }
#pragma unroll
    for (int o = 16; o; o >>= 1) s += __shfl_xor_sync(0xffffffffu, s, o);
    float r = 1.f / s;
#pragma unroll
    for (int u = 0; u < 16; u++) v[u] *= r;
}

__global__ void softmax_kernel()
{
    int gw = (blockIdx.x * blockDim.x + threadIdx.x) >> 5;
    int lane = threadIdx.x & 31;
    size_t base = (size_t)gw * CC;
    float t1[16], t2[16], t3[16], sr[16], si[16], pr[16], pi[16];
#pragma unroll
    for (int u = 0; u < 16; u++) {
        int c = lane + u * 32;
        t1[u] = g_S[0 * PS + base + c];
        t2[u] = g_S[1 * PS + base + c];
        t3[u] = g_S[2 * PS + base + c];
    }
#pragma unroll
    for (int u = 0; u < 16; u++) {
        sr[u] = (t1[u] - t2[u]) * ATTN_SCALE;
        si[u] = (t3[u] - t1[u] - t2[u]) * ATTN_SCALE;
    }
    softmax16(sr);
    softmax16(si);
#pragma unroll
    for (int u = 0; u < 16; u++) { pr[u] = sr[u]; pi[u] = si[u]; }
#pragma unroll
    for (int u = 0; u < 16; u++) {
        int c = lane + u * 32;
        t1[u] = g_S[3 * PS + base + c];
        t2[u] = g_S[4 * PS + base + c];
        t3[u] = g_S[5 * PS + base + c];
    }
#pragma unroll
    for (int u = 0; u < 16; u++) {
        sr[u] = (t1[u] - t2[u]) * ATTN_SCALE;
        si[u] = (t3[u] - t1[u] - t2[u]) * ATTN_SCALE;
    }
    softmax16(sr);
    softmax16(si);
    int brow = (gw >> 9) << 9;   // b * CC
    float xr = 0.f;
#pragma unroll
    for (int u = 0; u < 16; u++) {
        int c = lane + u * 32;
        float prf = pr[u] + sr[u], pif = pi[u] + si[u];
        size_t d = (size_t)gw * 1024 + c;
        g_P[d]       = __float2half_rn(prf);
        g_P[d + 512] = __float2half_rn(pif);
        xr += prf * g_ny[0 * MTOT + brow + c] - pif * g_ny[1 * MTOT + brow + c];
    }
#pragma unroll
    for (int o = 16; o; o >>= 1) xr += __shfl_xor_sync(0xffffffffu, xr, o);
    if (lane == 0) g_Xny[gw] = xr;
}

// ---------------- attnv: X = P @ vt^T, 256x128 engine, K=1024 ----------------
__global__ __launch_bounds__(512, 1) void attnv_mma()
{
    GEMM_PRE();
    int z = blockIdx.z;
    int b = z >> 1, pl = z & 1;
    int n0 = blockIdx.x * 128, m0 = blockIdx.y * 256;
    GS g;
    g.A = g_P + (size_t)(b * CC + m0) * 1024;
    g.B = g_vt + ((size_t)(b * 2 + pl) * 256 + n0) * 1024;
    g.lda = 1024; g.ldb = 1024; g.nkc = 16;
    gemmS_run(g, acc, base);
#pragma unroll
    for (int mt = 0; mt < 4; mt++) {
#pragma unroll
        for (int nt = 0; nt < 4; nt++) {
            int col = n0 + wc * 32 + nt * 8 + gc * 2;
#pragma unroll
            for (int h = 0; h < 2; h++) {
                int row = m0 + wr * 64 + mt * 16 + gr + h * 8;
                size_t d = (size_t)(b * CC + row) * XW + (size_t)pl * 256 + col;
                __half2 v = __floats2half2_rn(acc[mt][nt][h * 2 + 0], acc[mt][nt][h * 2 + 1]);
                *(__half2*)&g_X[d] = v;
            }
        }
    }
}

// ---------------- irfft: out = X @ CT^T (K=512) + Nyquist rank-1 ----------------
__global__ __launch_bounds__(512, 1) void irfft_mma(float* __restrict__ out)
{
    GEMM_PRE();
    __shared__ float sXny[256];
    int n0 = blockIdx.x * 128, m0 = blockIdx.y * 256;
    if (threadIdx.x < 256) sXny[threadIdx.x] = g_Xny[m0 + threadIdx.x];
    GS g;
    g.A = g_X + (size_t)m0 * XW;
    g.B = g_CT + (size_t)n0 * XW;
    g.lda = XW; g.ldb = XW; g.nkc = 8;
    gemmS_run(g, acc, base);
#pragma unroll
    for (int mt = 0; mt < 4; mt++) {
#pragma unroll
        for (int nt = 0; nt < 4; nt++) {
            int col = n0 + wc * 32 + nt * 8 + gc * 2;
            float w0 = (col & 1) ? -INV_SQRT_S : INV_SQRT_S;
#pragma unroll
            for (int h = 0; h < 2; h++) {
                int rl = wr * 64 + mt * 16 + gr + h * 8;
                float xny = sXny[rl];
                int row = m0 + rl;
                *(float2*)&out[(size_t)row * SS + col] =
                    make_float2(acc[mt][nt][h * 2 + 0] + xny * w0,
                                acc[mt][nt][h * 2 + 1] - xny * w0);
            }
        }
    }
}

// ---------------- launch ----------------

extern "C" void kernel_launch(void* const* d_in, const int* in_sizes, int n_in,
                              void* d_out, int out_size)
{
    const float* x   = (const float*)d_in[0];
    const float* l1r = (const float*)d_in[1];
    const float* l1i = (const float*)d_in[2];
    const float* h1r = (const float*)d_in[3];
    const float* h1i = (const float*)d_in[4];
    const float* lbr = (const float*)d_in[5];
    const float* lbi = (const float*)d_in[6];
    const float* hbr = (const float*)d_in[7];
    const float* hbi = (const float*)d_in[8];
    float* out = (float*)d_out;

    cudaFuncSetAttribute(proj_mma,  cudaFuncAttributeMaxDynamicSharedMemorySize, MMA_SMEMF);
    cudaFuncSetAttribute(score_mma, cudaFuncAttributeMaxDynamicSharedMemorySize, MMA_SMEMF);
    cudaFuncSetAttribute(attnv_mma, cudaFuncAttributeMaxDynamicSharedMemorySize, MMA_SMEMS);
    cudaFuncSetAttribute(irfft_mma, cudaFuncAttributeMaxDynamicSharedMemorySize, MMA_SMEMS);

    // launch order chosen so ncu (-s 5 -c 1) profiles score_mma (index 5)
    build_w_kernel<<<512, 256>>>(l1r, l1i, h1r, h1i);                        // 0
    build_bias_kernel<<<(NWP + 255) / 256, 256>>>(lbr, lbi, hbr, hbi);       // 1
    splitx_ny_kernel<<<MTOT / 8, 256>>>(x, lbr, lbi, hbr, hbi);              // 2
    proj_mma<<<dim3(NWP / 128, MTOT / 256), 512, MMA_SMEMF>>>();             // 3 (8, 128)
    vt_kernel<<<dim3(CC / 32, 256 / 32, BB), dim3(32, 8)>>>();               // 4
    score_mma<<<dim3(4, 2, BB * 6), 512, MMA_SMEMF>>>();                     // 5 <- profiled
    softmax_kernel<<<MTOT / 8, 256>>>();                                     // 6
    build_ct_kernel<<<(SS * XW + 255) / 256, 256>>>();                       // 7
    attnv_mma<<<dim3(2, 2, BB * 2), 512, MMA_SMEMS>>>();                     // 8
    irfft_mma<<<dim3(4, MTOT / 256), 512, MMA_SMEMS>>>(out);                 // 9
}

// round 16
// speedup vs baseline: 1.2125x; 1.2125x over previous
#include <cuda_runtime.h>
#include <cuda_fp16.h>
#include <cstdint>
#include <math.h>

// ---------------- problem constants ----------------
#define BB 64
#define CC 512
#define SS 512
#define EE 257
#define MTOT (BB*CC)                 // 32768
#define KP  256                      // low-plane row stride (e<256 only)
#define PSL ((size_t)MTOT*KP)
#define NWP 1024                     // proj N = 4*256
#define XW  512                      // packed X row stride / irfft K
#define PS  ((size_t)BB*CC*CC)

#define INV_SQRT_S 0.04419417382415922f
#define TWO_PI_OVER_S 0.01227184630308513f
#define ATTN_SCALE 0.06237828615518053f   // 1/sqrt(257)

// ---------------- scratch (static device globals) ----------------
__device__ __align__(256) float g_bias[NWP];
__device__ __align__(256) float g_Wny[4*SS];
__device__ __align__(256) float g_ny[4*MTOT];
__device__ __align__(256) float g_S[6*PS];
__device__ __align__(256) float g_Xny[MTOT];
__device__ __align__(256) __half g_xh[(size_t)MTOT*SS];
__device__ __align__(256) __half g_xl[(size_t)MTOT*SS];
__device__ __align__(256) __half g_WTh[NWP*SS];
__device__ __align__(256) __half g_WTl[NWP*SS];
__device__ __align__(256) __half g_CT[SS*XW];
__device__ __align__(256) __half g_lowh[6*PSL];
__device__ __align__(256) __half g_lowl[6*PSL];
__device__ __align__(256) __half g_P[(size_t)MTOT*1024];
__device__ __align__(256) __half g_vt[(size_t)BB*2*256*1024];
__device__ __align__(256) __half g_X[(size_t)MTOT*XW];

// ---------------- helpers ----------------
__device__ __forceinline__ uint32_t smem_u32(const void* p) {
    uint32_t a;
    asm("{ .reg .u64 t; cvta.to.shared.u64 t, %1; cvt.u32.u64 %0, t; }" : "=r"(a) : "l"(p));
    return a;
}
__device__ __forceinline__ void hsplit(float v, __half* h, __half* l) {
    __half a = __float2half_rn(v);
    *h = a;
    *l = __float2half_rn(v - __half2float(a));
}
__device__ __forceinline__ void ldsm4(uint32_t (&r)[4], uint32_t a) {
    asm volatile("ldmatrix.sync.aligned.m8n8.x4.shared.b16 {%0,%1,%2,%3}, [%4];"
                 : "=r"(r[0]), "=r"(r[1]), "=r"(r[2]), "=r"(r[3]) : "r"(a));
}
__device__ __forceinline__ void mma16816b(float (&d)[4], const uint32_t (&a)[4],
                                          uint32_t b0, uint32_t b1) {
    asm volatile(
        "mma.sync.aligned.m16n8k16.row.col.f32.f16.f16.f32 "
        "{%0,%1,%2,%3},{%4,%5,%6,%7},{%8,%9},{%0,%1,%2,%3};"
        : "+f"(d[0]), "+f"(d[1]), "+f"(d[2]), "+f"(d[3])
        : "r"(a[0]), "r"(a[1]), "r"(a[2]), "r"(a[3]), "r"(b0), "r"(b1));
}
__device__ __forceinline__ void cpasync16(uint32_t s, const void* g) {
    asm volatile("cp.async.cg.shared.global [%0], [%1], 16;" :: "r"(s), "l"(g));
}
__device__ __forceinline__ void wait_upto(int n) {
    if (n >= 2)      asm volatile("cp.async.wait_group 2;");
    else if (n == 1) asm volatile("cp.async.wait_group 1;");
    else             asm volatile("cp.async.wait_group 0;");
}
__device__ __forceinline__ float plane256(int pn, int r) {
    if (pn == 4) return g_ny[0 * MTOT + r] + g_ny[1 * MTOT + r];
    if (pn == 5) return g_ny[2 * MTOT + r] + g_ny[3 * MTOT + r];
    return g_ny[pn * MTOT + r];
}

// ---------------- builder kernels (R14 layout: WT row = p*256+e) ----------------

__global__ void build_w_kernel(const float* __restrict__ l1r, const float* __restrict__ l1i,
                               const float* __restrict__ h1r, const float* __restrict__ h1i)
{
    __shared__ float cr[257], ci[257];
    int s = blockIdx.x;
    for (int k = threadIdx.x; k < 257; k += blockDim.x) {
        int idx = (s * k) & 511;
        float ang = (float)idx * TWO_PI_OVER_S;
        float sn, cs;
        sincosf(ang, &sn, &cs);
        cr[k] = cs * INV_SQRT_S;
        ci[k] = -sn * INV_SQRT_S;
    }
    __syncthreads();
    for (int e = threadIdx.x; e < EE; e += blockDim.x) {
        float wlr = 0.f, wli = 0.f, whr = 0.f, whi = 0.f;
        for (int k = 0; k < 128; k++) {
            float ar = cr[k], ai = ci[k];
            float br = l1r[k * EE + e], bi = l1i[k * EE + e];
            wlr += ar * br - ai * bi;
            wli += ar * bi + ai * br;
        }
        for (int k = 0; k < 129; k++) {
            float ar = cr[128 + k], ai = ci[128 + k];
            float br = h1r[k * EE + e], bi = h1i[k * EE + e];
            whr += ar * br - ai * bi;
            whi += ar * bi + ai * br;
        }
        if (e < 256) {
            hsplit(wlr, &g_WTh[(0 * 256 + e) * SS + s], &g_WTl[(0 * 256 + e) * SS + s]);
            hsplit(wli, &g_WTh[(1 * 256 + e) * SS + s], &g_WTl[(1 * 256 + e) * SS + s]);
            hsplit(whr, &g_WTh[(2 * 256 + e) * SS + s], &g_WTl[(2 * 256 + e) * SS + s]);
            hsplit(whi, &g_WTh[(3 * 256 + e) * SS + s], &g_WTl[(3 * 256 + e) * SS + s]);
        } else {
            g_Wny[0 * SS + s] = wlr;
            g_Wny[1 * SS + s] = wli;
            g_Wny[2 * SS + s] = whr;
            g_Wny[3 * SS + s] = whi;
        }
    }
}

__global__ void build_bias_kernel(const float* __restrict__ lbr, const float* __restrict__ lbi,
                                  const float* __restrict__ hbr, const float* __restrict__ hbi)
{
    int n = blockIdx.x * blockDim.x + threadIdx.x;
    if (n >= NWP) return;
    int p = n >> 8, e = n & 255;
    const float* src = (p == 0) ? lbr : (p == 1) ? lbi : (p == 2) ? hbr : hbi;
    g_bias[n] = src[e];
}

__global__ void splitx_ny_kernel(const float* __restrict__ x,
                                 const float* __restrict__ lbr, const float* __restrict__ lbi,
                                 const float* __restrict__ hbr, const float* __restrict__ hbi)
{
    __shared__ float sW[4][512];
    __shared__ float sb[4];
    int t = threadIdx.x;
    for (int i = t; i < 4 * 512; i += 256) sW[i >> 9][i & 511] = g_Wny[i];
    if (t == 0) { sb[0] = lbr[256]; sb[1] = lbi[256]; sb[2] = hbr[256]; sb[3] = hbi[256]; }
    __syncthreads();
    int warp = t >> 5, lane = t & 31;
    int row = blockIdx.x * 8 + warp;
    const float* xr = x + (size_t)row * SS;
    float a0 = 0.f, a1 = 0.f, a2 = 0.f, a3 = 0.f;
#pragma unroll
    for (int i = 0; i < 4; i++) {
        int s = i * 128 + lane * 4;
        float4 v = *(const float4*)(xr + s);
        float vv[4] = {v.x, v.y, v.z, v.w};
        __half hh[4], ll[4];
#pragma unroll
        for (int j = 0; j < 4; j++) {
            hsplit(vv[j], &hh[j], &ll[j]);
            a0 += vv[j] * sW[0][s + j];
            a1 += vv[j] * sW[1][s + j];
            a2 += vv[j] * sW[2][s + j];
            a3 += vv[j] * sW[3][s + j];
        }
        size_t d = (size_t)row * SS + s;
        *(__half2*)&g_xh[d]     = __halves2half2(hh[0], hh[1]);
        *(__half2*)&g_xh[d + 2] = __halves2half2(hh[2], hh[3]);
        *(__half2*)&g_xl[d]     = __halves2half2(ll[0], ll[1]);
        *(__half2*)&g_xl[d + 2] = __halves2half2(ll[2], ll[3]);
    }
#pragma unroll
    for (int o = 16; o; o >>= 1) {
        a0 += __shfl_xor_sync(0xffffffffu, a0, o);
        a1 += __shfl_xor_sync(0xffffffffu, a1, o);
        a2 += __shfl_xor_sync(0xffffffffu, a2, o);
        a3 += __shfl_xor_sync(0xffffffffu, a3, o);
    }
    if (lane == 0) {
        g_ny[0 * MTOT + row] = fmaxf(a0 + sb[0], 0.f);
        g_ny[1 * MTOT + row] = fmaxf(a1 + sb[1], 0.f);
        g_ny[2 * MTOT + row] = fmaxf(a2 + sb[2], 0.f);
        g_ny[3 * MTOT + row] = fmaxf(a3 + sb[3], 0.f);
    }
}

__global__ void build_ct_kernel()
{
    int idx = blockIdx.x * blockDim.x + threadIdx.x;
    if (idx >= SS * XW) return;
    int s = idx / XW, k = idx - s * XW;
    float v;
    if (k < 256) {
        int e = k;
        float w = (e == 0) ? 1.f : 2.f;
        float ang = (float)((e * s) & 511) * TWO_PI_OVER_S;
        v = w * cosf(ang) * INV_SQRT_S;
    } else {
        int e = k - 256;
        if (e == 0) v = 0.f;
        else {
            float ang = (float)((e * s) & 511) * TWO_PI_OVER_S;
            v = -2.f * sinf(ang) * INV_SQRT_S;
        }
    }
    g_CT[idx] = __float2half_rn(v);
}

__global__ void sum_kernel()
{
    size_t i = (size_t)blockIdx.x * blockDim.x + threadIdx.x;
    if (i >= PSL) return;
    float lr = __half2float(g_lowh[0 * PSL + i]) + __half2float(g_lowl[0 * PSL + i]);
    float li = __half2float(g_lowh[1 * PSL + i]) + __half2float(g_lowl[1 * PSL + i]);
    float hr = __half2float(g_lowh[2 * PSL + i]) + __half2float(g_lowl[2 * PSL + i]);
    float hi = __half2float(g_lowh[3 * PSL + i]) + __half2float(g_lowl[3 * PSL + i]);
    hsplit(lr + li, &g_lowh[4 * PSL + i], &g_lowl[4 * PSL + i]);
    hsplit(hr + hi, &g_lowh[5 * PSL + i], &g_lowl[5 * PSL + i]);
}

__global__ void vt_kernel()
{
    __shared__ float tr[32][33], ti[32][33];
    int b = blockIdx.z, e0 = blockIdx.y * 32, c0 = blockIdx.x * 32;
    int tx = threadIdx.x, ty = threadIdx.y;
    for (int r = ty; r < 32; r += 8) {
        size_t src = ((size_t)(b * CC + c0 + r)) * KP + (e0 + tx);
        tr[r][tx] = __half2float(g_lowh[0 * PSL + src]) + __half2float(g_lowl[0 * PSL + src]);
        ti[r][tx] = __half2float(g_lowh[1 * PSL + src]) + __half2float(g_lowl[1 * PSL + src]);
    }
    __syncthreads();
    for (int r = ty; r < 32; r += 8) {
        int n = e0 + r, c = c0 + tx;
        float lr = tr[tx][r], li = ti[tx][r];
        size_t d0 = ((size_t)(b * 2 + 0) * 256 + n) * 1024;
        size_t d1 = ((size_t)(b * 2 + 1) * 256 + n) * 1024;
        g_vt[d0 + c]       = __float2half_rn(lr);
        g_vt[d0 + 512 + c] = __float2half_rn(-li);
        g_vt[d1 + c]       = __float2half_rn(li);
        g_vt[d1 + 512 + c] = __float2half_rn(lr);
    }
}

// ============ FUSED 3-product engine: 256x128 tile, 512 threads ============
// K-chunk 32, 4 stages x 48KB, prefetch depth 3, wait_group 2.

struct GF {
    const __half *Ah, *Al, *Bh, *Bl;
    int lda, ldb, nkc;
};

#define FSTG 49152u

__device__ __forceinline__ void gloadF(const GF& g, int kc, int stg, uint32_t base, int t)
{
    uint32_t sb = base + (uint32_t)stg * FSTG;
    int rA = t >> 1, cA2 = (t & 1) * 2;
    const __half* gAh = g.Ah + (size_t)rA * g.lda + kc * 32 + cA2 * 8;
    const __half* gAl = g.Al + (size_t)rA * g.lda + kc * 32 + cA2 * 8;
    uint32_t mA = (uint32_t)((rA >> 1) & 3);
    uint32_t sAh = sb + (uint32_t)rA * 64u;
    uint32_t sAl = sAh + 16384u;
#pragma unroll
    for (int i = 0; i < 2; i++) {
        uint32_t c = (uint32_t)(cA2 + i);
        uint32_t sw = (c ^ mA) << 4;
        cpasync16(sAh + sw, gAh + i * 8);
        cpasync16(sAl + sw, gAl + i * 8);
    }
    int rB = t >> 2, cB = t & 3;
    const __half* gBh = g.Bh + (size_t)rB * g.ldb + kc * 32 + cB * 8;
    const __half* gBl = g.Bl + (size_t)rB * g.ldb + kc * 32 + cB * 8;
    uint32_t swB = (uint32_t)((cB ^ ((rB >> 1) & 3)) << 4);
    uint32_t sBh = sb + 32768u + (uint32_t)rB * 64u;
    uint32_t sBl = sBh + 8192u;
    cpasync16(sBh + swB, gBh);
    cpasync16(sBl + swB, gBl);
    asm volatile("cp.async.commit_group;");
}

__device__ __forceinline__ void gemmF_run(const GF& g, float (&acc)[4][4][4], uint32_t base)
{
    const int t = threadIdx.x;
    const int warp = t >> 5, lane = t & 31;
    const int wr = warp >> 2, wc = warp & 3;
    const int nkc = g.nkc;

    gloadF(g, 0, 0, base, t);
    if (nkc > 1) gloadF(g, 1, 1, base, t);
    if (nkc > 2) gloadF(g, 2, 2, base, t);
    for (int ch = 0; ch < nkc; ch++) {
        wait_upto(nkc - 1 - ch);
        __syncthreads();
        if (ch + 3 < nkc) gloadF(g, ch + 3, (ch + 3) & 3, base, t);
        uint32_t sb = base + (uint32_t)(ch & 3) * FSTG;
        uint32_t sAh = sb, sAl = sb + 16384u, sBh = sb + 32768u, sBl = sb + 40960u;
#pragma unroll
        for (int s = 0; s < 2; s++) {
            uint32_t aoffv[4], boffv[2];
#pragma unroll
            for (int mt = 0; mt < 4; mt++) {
                int row = wr * 64 + mt * 16 + (lane & 15);
                uint32_t u = (uint32_t)(s * 2 + (lane >> 4));
                aoffv[mt] = (uint32_t)row * 64u + (((u ^ ((uint32_t)(row >> 1) & 3u))) << 4);
            }
#pragma unroll
            for (int ntp = 0; ntp < 2; ntp++) {
                int row = wc * 32 + ntp * 16 + (((lane >> 4) & 1) << 3) + (lane & 7);
                uint32_t u = (uint32_t)(s * 2 + ((lane >> 3) & 1));
                boffv[ntp] = (uint32_t)row * 64u + (((u ^ ((uint32_t)(row >> 1) & 3u))) << 4);
            }
            uint32_t a[4][4], bh[2][4], bl[2][4];
#pragma unroll
            for (int mt = 0; mt < 4; mt++) ldsm4(a[mt], sAh + aoffv[mt]);
#pragma unroll
            for (int ntp = 0; ntp < 2; ntp++) {
                ldsm4(bh[ntp], sBh + boffv[ntp]);
                ldsm4(bl[ntp], sBl + boffv[ntp]);
            }
#pragma unroll
            for (int mt = 0; mt < 4; mt++)
#pragma unroll
                for (int nt = 0; nt < 4; nt++)
                    mma16816b(acc[mt][nt], a[mt], bh[nt >> 1][(nt & 1) * 2],
                              bh[nt >> 1][(nt & 1) * 2 + 1]);
#pragma unroll
            for (int mt = 0; mt < 4; mt++)
#pragma unroll
                for (int nt = 0; nt < 4; nt++)
                    mma16816b(acc[mt][nt], a[mt], bl[nt >> 1][(nt & 1) * 2],
                              bl[nt >> 1][(nt & 1) * 2 + 1]);
#pragma unroll
            for (int mt = 0; mt < 4; mt++) ldsm4(a[mt], sAl + aoffv[mt]);
#pragma unroll
            for (int mt = 0; mt < 4; mt++)
#pragma unroll
                for (int nt = 0; nt < 4; nt++)
                    mma16816b(acc[mt][nt], a[mt], bh[nt >> 1][(nt & 1) * 2],
                              bh[nt >> 1][(nt & 1) * 2 + 1]);
        }
    }
    __syncthreads();
}

#define MMA_SMEMF (4 * FSTG + 128)

// ============ single-product 256x128 engine, 512 threads, 4 stages ============

struct GS {
    const __half *A, *B;
    int lda, ldb, nkc;
};

#define SSTG 49152u

__device__ __forceinline__ void gloadS(const GS& g, int kc, int stg, uint32_t base, int t)
{
    uint32_t sb = base + (uint32_t)stg * SSTG;
    int rA = t >> 1, cA = (t & 1) * 4;
    const __half* gA = g.A + (size_t)rA * g.lda + kc * 64 + cA * 8;
    uint32_t sA = sb + (uint32_t)rA * 128u;
#pragma unroll
    for (int i = 0; i < 4; i++) {
        int c = cA + i;
        uint32_t sw = (uint32_t)((c ^ (rA & 7)) << 4);
        cpasync16(sA + sw, gA + i * 8);
    }
    int rB = t >> 2, cB = (t & 3) * 2;
    const __half* gB = g.B + (size_t)rB * g.ldb + kc * 64 + cB * 8;
    uint32_t sB = sb + 32768u + (uint32_t)rB * 128u;
#pragma unroll
    for (int i = 0; i < 2; i++) {
        int c = cB + i;
        uint32_t sw = (uint32_t)((c ^ (rB & 7)) << 4);
        cpasync16(sB + sw, gB + i * 8);
    }
    asm volatile("cp.async.commit_group;");
}

__device__ __forceinline__ void gemmS_run(const GS& g, float (&acc)[4][4][4], uint32_t base)
{
    const int t = threadIdx.x;
    const int warp = t >> 5, lane = t & 31;
    const int wr = warp >> 2, wc = warp & 3;
    const int nkc = g.nkc;

    gloadS(g, 0, 0, base, t);
    if (nkc > 1) gloadS(g, 1, 1, base, t);
    if (nkc > 2) gloadS(g, 2, 2, base, t);
    for (int ch = 0; ch < nkc; ch++) {
        wait_upto(nkc - 1 - ch);
        __syncthreads();
        if (ch + 3 < nkc) gloadS(g, ch + 3, (ch + 3) & 3, base, t);
        uint32_t sb = base + (uint32_t)(ch & 3) * SSTG;
        uint32_t sA = sb, sB = sb + 32768u;
#pragma unroll
        for (int s = 0; s < 4; s++) {
            uint32_t a[4][4], b[2][4];
#pragma unroll
            for (int mt = 0; mt < 4; mt++) {
                int row = wr * 64 + mt * 16 + (lane & 15);
                int u = s * 2 + (lane >> 4);
                ldsm4(a[mt], sA + (uint32_t)row * 128u + (uint32_t)((u ^ (row & 7)) << 4));
            }
#pragma unroll
            for (int ntp = 0; ntp < 2; ntp++) {
                int row = wc * 32 + ntp * 16 + (((lane >> 4) & 1) << 3) + (lane & 7);
                int u = s * 2 + ((lane >> 3) & 1);
                ldsm4(b[ntp], sB + (uint32_t)row * 128u + (uint32_t)((u ^ (row & 7)) << 4));
            }
#pragma unroll
            for (int mt = 0; mt < 4; mt++)
#pragma unroll
                for (int nt = 0; nt < 4; nt++)
                    mma16816b(acc[mt][nt], a[mt], b[nt >> 1][(nt & 1) * 2],
                              b[nt >> 1][(nt & 1) * 2 + 1]);
        }
    }
    __syncthreads();
}

#define MMA_SMEMS (4 * SSTG + 128)

#define GEMM_PRE() \
    extern __shared__ char dynsm[]; \
    uint32_t raw = smem_u32(dynsm); \
    uint32_t base = (raw + 127u) & ~127u; \
    char* smp = dynsm + (base - raw); \
    (void)smp; \
    float acc[4][4][4]; \
    for (int i = 0; i < 4; i++) for (int j = 0; j < 4; j++) for (int q = 0; q < 4; q++) acc[i][j][q] = 0.f; \
    const int warp = threadIdx.x >> 5, lane = threadIdx.x & 31; \
    const int wr = warp >> 2, wc = warp & 3; \
    const int gr = lane >> 2, gc = lane & 3;

// ---------------- proj: relu(x@W + bias), fused 256x128 (R14 epilogue) ----------------
__global__ __launch_bounds__(512, 1) void proj_mma()
{
    GEMM_PRE();
    int n0 = blockIdx.x * 128, m0 = blockIdx.y * 256;
    GF g;
    g.Ah = g_xh + (size_t)m0 * SS;   g.Al = g_xl + (size_t)m0 * SS;
    g.Bh = g_WTh + (size_t)n0 * SS;  g.Bl = g_WTl + (size_t)n0 * SS;
    g.lda = SS; g.ldb = SS; g.nkc = 16;
    gemmF_run(g, acc, base);
#pragma unroll
    for (int mt = 0; mt < 4; mt++) {
#pragma unroll
        for (int nt = 0; nt < 4; nt++) {
            int col = n0 + wc * 32 + nt * 8 + gc * 2;
            int p = col >> 8, e = col & 255;
            float b0 = g_bias[col], b1 = g_bias[col + 1];
#pragma unroll
            for (int h = 0; h < 2; h++) {
                int row = m0 + wr * 64 + mt * 16 + gr + h * 8;
                float v0 = fmaxf(acc[mt][nt][h * 2 + 0] + b0, 0.f);
                float v1 = fmaxf(acc[mt][nt][h * 2 + 1] + b1, 0.f);
                size_t d = (size_t)p * PSL + (size_t)row * KP + e;
                __half h0, l0, h1, l1;
                hsplit(v0, &h0, &l0);
                hsplit(v1, &h1, &l1);
                *(__half2*)&g_lowh[d] = __halves2half2(h0, h1);
                *(__half2*)&g_lowl[d] = __halves2half2(l0, l1);
            }
        }
    }
}

// ---------------- score: 6 Karatsuba planes, fused, symmetric-skip + rank-1 ----------------
// Symmetric planes: tiles (0, n_t in {2,3}) also write their transpose through smem
// (replaces the mirror kernel).
__global__ __launch_bounds__(512, 1) void score_mma()
{
    int z = blockIdx.z;
    int b = z / 6, which = z - b * 6;
    int hi = (which >= 3) ? 1 : 0;
    int w = which - 3 * hi;
    int apn = (w == 2) ? 4 : w;
    int bpn = hi ? ((w == 2) ? 5 : w + 2) : apn;
    int m_t, n_t;
    bool dotrans = false;
    if (!hi) {
        int tid8 = blockIdx.y * 4 + blockIdx.x;
        if (tid8 >= 6) return;
        const int mts[6] = {0, 0, 0, 0, 1, 1};
        const int nts[6] = {0, 1, 2, 3, 2, 3};
        m_t = mts[tid8]; n_t = nts[tid8];
        dotrans = (tid8 == 2 || tid8 == 3);
    } else {
        m_t = blockIdx.y; n_t = blockIdx.x;
    }
    GEMM_PRE();
    __shared__ float sA256[256], sB256[128];
    int m0 = m_t * 256, n0 = n_t * 128;
    if (threadIdx.x < 256)
        sA256[threadIdx.x] = plane256(apn, b * CC + m0 + threadIdx.x);
    else if (threadIdx.x < 384)
        sB256[threadIdx.x - 256] = plane256(bpn, b * CC + n0 + threadIdx.x - 256);
    size_t aoff = (size_t)apn * PSL + (size_t)(b * CC + m0) * KP;
    size_t boff = (size_t)bpn * PSL + (size_t)(b * CC + n0) * KP;
    GF g;
    g.Ah = g_lowh + aoff;  g.Al = g_lowl + aoff;
    g.Bh = g_lowh + boff;  g.Bl = g_lowl + boff;
    g.lda = KP; g.ldb = KP; g.nkc = 8;
    gemmF_run(g, acc, base);
    float* out = g_S + (size_t)which * PS + (size_t)(b * CC) * CC;
#pragma unroll
    for (int mt = 0; mt < 4; mt++) {
#pragma unroll
        for (int nt = 0; nt < 4; nt++) {
            int cl = wc * 32 + nt * 8 + gc * 2;
            float bv0 = sB256[cl], bv1 = sB256[cl + 1];
            int col = n0 + cl;
#pragma unroll
            for (int h = 0; h < 2; h++) {
                int rl = wr * 64 + mt * 16 + gr + h * 8;
                float av = sA256[rl];
                int row = m0 + rl;
                *(float2*)&out[(size_t)row * CC + col] =
                    make_float2(acc[mt][nt][h * 2 + 0] + av * bv0,
                                acc[mt][nt][h * 2 + 1] + av * bv1);
            }
        }
    }
    if (dotrans) {
        float* T = (float*)smp;   // [128][132]
        for (int h2 = 0; h2 < 2; h2++) {
            __syncthreads();
            if ((wr >> 1) == h2) {
#pragma unroll
                for (int mt = 0; mt < 4; mt++) {
#pragma unroll
                    for (int nt = 0; nt < 4; nt++) {
                        int cl = wc * 32 + nt * 8 + gc * 2;
                        float bv0 = sB256[cl], bv1 = sB256[cl + 1];
#pragma unroll
                        for (int h = 0; h < 2; h++) {
                            int rl = wr * 64 + mt * 16 + gr + h * 8;
                            int j = rl - h2 * 128;
                            float av = sA256[rl];
                            T[cl * 132 + j]       = acc[mt][nt][h * 2 + 0] + av * bv0;
                            T[(cl + 1) * 132 + j] = acc[mt][nt][h * 2 + 1] + av * bv1;
                        }
                    }
                }
            }
            __syncthreads();
            for (int idx = threadIdx.x; idx < 128 * 32; idx += 512) {
                int c = idx >> 5, q = idx & 31;
                float4 v = *(float4*)&T[c * 132 + q * 4];
                *(float4*)&out[(size_t)(n0 + c) * CC + (h2 * 128 + q * 4)] = v;
            }
        }
    }
}

// ---------------- softmax + Karatsuba combine -> P fp16 [Pr|Pi]; also xr[256] ----------------
__device__ __forceinline__ void softmax16(float (&v)[16])
{
    float m = -3.4e38f;
#pragma unroll
    for (int u = 0; u < 16; u++) m = fmaxf(m, v[u]);
#pragma unroll
    for (int o = 16; o; o >>= 1) m = fmaxf(m, __shfl_xor_sync(0xffffffffu, m, o));
    float s = 0.f;
#pragma unroll
    for (int u = 0; u < 16; u++) { v[u] = expf(v[u] - m); s += v[u]; }
#pragma unroll
    for (int o = 16; o; o >>= 1) s += __shfl_xor_sync(0xffffffffu, s, o);
    float r = 1.f / s;
#pragma unroll
    for (int u = 0; u < 16; u++) v[u] *= r;
}

__global__ void softmax_kernel()
{
    int gw = (blockIdx.x * blockDim.x + threadIdx.x) >> 5;
    int lane = threadIdx.x & 31;
    size_t base = (size_t)gw * CC;
    float t1[16], t2[16], t3[16], sr[16], si[16], pr[16], pi[16];
#pragma unroll
    for (int u = 0; u < 16; u++) {
        int c = lane + u * 32;
        t1[u] = g_S[0 * PS + base + c];
        t2[u] = g_S[1 * PS + base + c];
        t3[u] = g_S[2 * PS + base + c];
    }
#pragma unroll
    for (int u = 0; u < 16; u++) {
        sr[u] = (t1[u] - t2[u]) * ATTN_SCALE;
        si[u] = (t3[u] - t1[u] - t2[u]) * ATTN_SCALE;
    }
    softmax16(sr);
    softmax16(si);
#pragma unroll
    for (int u = 0; u < 16; u++) { pr[u] = sr[u]; pi[u] = si[u]; }
#pragma unroll
    for (int u = 0; u < 16; u++) {
        int c = lane + u * 32;
        t1[u] = g_S[3 * PS + base + c];
        t2[u] = g_S[4 * PS + base + c];
        t3[u] = g_S[5 * PS + base + c];
    }
#pragma unroll
    for (int u = 0; u < 16; u++) {
        sr[u] = (t1[u] - t2[u]) * ATTN_SCALE;
        si[u] = (t3[u] - t1[u] - t2[u]) * ATTN_SCALE;
    }
    softmax16(sr);
    softmax16(si);
    int brow = (gw >> 9) << 9;   // b * CC
    float xr = 0.f;
#pragma unroll
    for (int u = 0; u < 16; u++) {
        int c = lane + u * 32;
        float prf = pr[u] + sr[u], pif = pi[u] + si[u];
        size_t d = (size_t)gw * 1024 + c;
        g_P[d]       = __float2half_rn(prf);
        g_P[d + 512] = __float2half_rn(pif);
        xr += prf * g_ny[0 * MTOT + brow + c] - pif * g_ny[1 * MTOT + brow + c];
    }
#pragma unroll
    for (int o = 16; o; o >>= 1) xr += __shfl_xor_sync(0xffffffffu, xr, o);
    if (lane == 0) g_Xny[gw] = xr;
}

// ---------------- attnv: X = P @ vt^T, 256x128 engine, K=1024 ----------------
__global__ __launch_bounds__(512, 1) void attnv_mma()
{
    GEMM_PRE();
    int z = blockIdx.z;
    int b = z >> 1, pl = z & 1;
    int n0 = blockIdx.x * 128, m0 = blockIdx.y * 256;
    GS g;
    g.A = g_P + (size_t)(b * CC + m0) * 1024;
    g.B = g_vt + ((size_t)(b * 2 + pl) * 256 + n0) * 1024;
    g.lda = 1024; g.ldb = 1024; g.nkc = 16;
    gemmS_run(g, acc, base);
#pragma unroll
    for (int mt = 0; mt < 4; mt++) {
#pragma unroll
        for (int nt = 0; nt < 4; nt++) {
            int col = n0 + wc * 32 + nt * 8 + gc * 2;
#pragma unroll
            for (int h = 0; h < 2; h++) {
                int row = m0 + wr * 64 + mt * 16 + gr + h * 8;
                size_t d = (size_t)(b * CC + row) * XW + (size_t)pl * 256 + col;
                __half2 v = __floats2half2_rn(acc[mt][nt][h * 2 + 0], acc[mt][nt][h * 2 + 1]);
                *(__half2*)&g_X[d] = v;
            }
        }
    }
}

// ---------------- irfft: out = X @ CT^T (K=512) + Nyquist rank-1 ----------------
__global__ __launch_bounds__(512, 1) void irfft_mma(float* __restrict__ out)
{
    GEMM_PRE();
    __shared__ float sXny[256];
    int n0 = blockIdx.x * 128, m0 = blockIdx.y * 256;
    if (threadIdx.x < 256) sXny[threadIdx.x] = g_Xny[m0 + threadIdx.x];
    GS g;
    g.A = g_X + (size_t)m0 * XW;
    g.B = g_CT + (size_t)n0 * XW;
    g.lda = XW; g.ldb = XW; g.nkc = 8;
    gemmS_run(g, acc, base);
#pragma unroll
    for (int mt = 0; mt < 4; mt++) {
#pragma unroll
        for (int nt = 0; nt < 4; nt++) {
            int col = n0 + wc * 32 + nt * 8 + gc * 2;
            float w0 = (col & 1) ? -INV_SQRT_S : INV_SQRT_S;
#pragma unroll
            for (int h = 0; h < 2; h++) {
                int rl = wr * 64 + mt * 16 + gr + h * 8;
                float xny = sXny[rl];
                int row = m0 + rl;
                *(float2*)&out[(size_t)row * SS + col] =
                    make_float2(acc[mt][nt][h * 2 + 0] + xny * w0,
                                acc[mt][nt][h * 2 + 1] - xny * w0);
            }
        }
    }
}

// ---------------- launch ----------------

extern "C" void kernel_launch(void* const* d_in, const int* in_sizes, int n_in,
                              void* d_out, int out_size)
{
    const float* x   = (const float*)d_in[0];
    const float* l1r = (const float*)d_in[1];
    const float* l1i = (const float*)d_in[2];
    const float* h1r = (const float*)d_in[3];
    const float* h1i = (const float*)d_in[4];
    const float* lbr = (const float*)d_in[5];
    const float* lbi = (const float*)d_in[6];
    const float* hbr = (const float*)d_in[7];
    const float* hbi = (const float*)d_in[8];
    float* out = (float*)d_out;

    cudaFuncSetAttribute(proj_mma,  cudaFuncAttributeMaxDynamicSharedMemorySize, MMA_SMEMF);
    cudaFuncSetAttribute(score_mma, cudaFuncAttributeMaxDynamicSharedMemorySize, MMA_SMEMF);
    cudaFuncSetAttribute(attnv_mma, cudaFuncAttributeMaxDynamicSharedMemorySize, MMA_SMEMS);
    cudaFuncSetAttribute(irfft_mma, cudaFuncAttributeMaxDynamicSharedMemorySize, MMA_SMEMS);

    // launch order chosen so ncu (-s 5 -c 1) profiles score_mma (index 5)
    build_w_kernel<<<512, 256>>>(l1r, l1i, h1r, h1i);                        // 0
    build_bias_kernel<<<(NWP + 255) / 256, 256>>>(lbr, lbi, hbr, hbi);       // 1
    splitx_ny_kernel<<<MTOT / 8, 256>>>(x, lbr, lbi, hbr, hbi);              // 2
    proj_mma<<<dim3(NWP / 128, MTOT / 256), 512, MMA_SMEMF>>>();             // 3 (8, 128)
    sum_kernel<<<(int)((PSL + 255) / 256), 256>>>();                         // 4
    score_mma<<<dim3(4, 2, BB * 6), 512, MMA_SMEMF>>>();                     // 5 <- profiled
    softmax_kernel<<<MTOT / 8, 256>>>();                                     // 6
    vt_kernel<<<dim3(CC / 32, 256 / 32, BB), dim3(32, 8)>>>();               // 7
    build_ct_kernel<<<(SS * XW + 255) / 256, 256>>>();                       // 8
    attnv_mma<<<dim3(2, 2, BB * 2), 512, MMA_SMEMS>>>();                     // 9
    irfft_mma<<<dim3(4, MTOT / 256), 512, MMA_SMEMS>>>(out);                 // 10
}

// round 17
// speedup vs baseline: 1.2146x; 1.0018x over previous
#include <cuda_runtime.h>
#include <cuda_fp16.h>
#include <cstdint>
#include <math.h>

// ---------------- problem constants ----------------
#define BB 64
#define CC 512
#define SS 512
#define EE 257
#define MTOT (BB*CC)                 // 32768
#define KP  256                      // low-plane row stride (e<256 only)
#define PSL ((size_t)MTOT*KP)
#define NWP 1024                     // proj N = 4*256
#define XW  512                      // packed X row stride / irfft K
#define PS  ((size_t)BB*CC*CC)

#define INV_SQRT_S 0.04419417382415922f
#define TWO_PI_OVER_S 0.01227184630308513f
#define ATTN_SCALE 0.06237828615518053f   // 1/sqrt(257)

// ---------------- scratch (static device globals) ----------------
__device__ __align__(256) float g_bias[NWP];
__device__ __align__(256) float g_Wny[4*SS];
__device__ __align__(256) float g_ny[4*MTOT];
__device__ __align__(256) float g_S[6*PS];
__device__ __align__(256) float g_Xny[MTOT];
__device__ __align__(256) __half g_xh[(size_t)MTOT*SS];
__device__ __align__(256) __half g_xl[(size_t)MTOT*SS];
__device__ __align__(256) __half g_WTh[NWP*SS];
__device__ __align__(256) __half g_WTl[NWP*SS];
__device__ __align__(256) __half g_CT[SS*XW];
__device__ __align__(256) __half g_lowh[6*PSL];
__device__ __align__(256) __half g_lowl[6*PSL];
__device__ __align__(256) __half g_P[(size_t)MTOT*1024];
__device__ __align__(256) __half g_vt[(size_t)BB*2*256*1024];
__device__ __align__(256) __half g_X[(size_t)MTOT*XW];

// ---------------- helpers ----------------
__device__ __forceinline__ uint32_t smem_u32(const void* p) {
    uint32_t a;
    asm("{ .reg .u64 t; cvta.to.shared.u64 t, %1; cvt.u32.u64 %0, t; }" : "=r"(a) : "l"(p));
    return a;
}
__device__ __forceinline__ void hsplit(float v, __half* h, __half* l) {
    __half a = __float2half_rn(v);
    *h = a;
    *l = __float2half_rn(v - __half2float(a));
}
__device__ __forceinline__ void ldsm4(uint32_t (&r)[4], uint32_t a) {
    asm volatile("ldmatrix.sync.aligned.m8n8.x4.shared.b16 {%0,%1,%2,%3}, [%4];"
                 : "=r"(r[0]), "=r"(r[1]), "=r"(r[2]), "=r"(r[3]) : "r"(a));
}
__device__ __forceinline__ void mma16816b(float (&d)[4], const uint32_t (&a)[4],
                                          uint32_t b0, uint32_t b1) {
    asm volatile(
        "mma.sync.aligned.m16n8k16.row.col.f32.f16.f16.f32 "
        "{%0,%1,%2,%3},{%4,%5,%6,%7},{%8,%9},{%0,%1,%2,%3};"
        : "+f"(d[0]), "+f"(d[1]), "+f"(d[2]), "+f"(d[3])
        : "r"(a[0]), "r"(a[1]), "r"(a[2]), "r"(a[3]), "r"(b0), "r"(b1));
}
__device__ __forceinline__ void cpasync16(uint32_t s, const void* g) {
    asm volatile("cp.async.cg.shared.global [%0], [%1], 16;" :: "r"(s), "l"(g));
}
__device__ __forceinline__ void wait_upto(int n) {
    if (n >= 2)      asm volatile("cp.async.wait_group 2;");
    else if (n == 1) asm volatile("cp.async.wait_group 1;");
    else             asm volatile("cp.async.wait_group 0;");
}
__device__ __forceinline__ float plane256(int pn, int r) {
    if (pn == 4) return g_ny[0 * MTOT + r] + g_ny[1 * MTOT + r];
    if (pn == 5) return g_ny[2 * MTOT + r] + g_ny[3 * MTOT + r];
    return g_ny[pn * MTOT + r];
}

// ---------------- builder kernels (WT row = p*256+e) ----------------

__global__ void build_w_kernel(const float* __restrict__ l1r, const float* __restrict__ l1i,
                               const float* __restrict__ h1r, const float* __restrict__ h1i)
{
    __shared__ float cr[257], ci[257];
    int s = blockIdx.x;
    for (int k = threadIdx.x; k < 257; k += blockDim.x) {
        int idx = (s * k) & 511;
        float ang = (float)idx * TWO_PI_OVER_S;
        float sn, cs;
        sincosf(ang, &sn, &cs);
        cr[k] = cs * INV_SQRT_S;
        ci[k] = -sn * INV_SQRT_S;
    }
    __syncthreads();
    for (int e = threadIdx.x; e < EE; e += blockDim.x) {
        float wlr = 0.f, wli = 0.f, whr = 0.f, whi = 0.f;
        for (int k = 0; k < 128; k++) {
            float ar = cr[k], ai = ci[k];
            float br = l1r[k * EE + e], bi = l1i[k * EE + e];
            wlr += ar * br - ai * bi;
            wli += ar * bi + ai * br;
        }
        for (int k = 0; k < 129; k++) {
            float ar = cr[128 + k], ai = ci[128 + k];
            float br = h1r[k * EE + e], bi = h1i[k * EE + e];
            whr += ar * br - ai * bi;
            whi += ar * bi + ai * br;
        }
        if (e < 256) {
            hsplit(wlr, &g_WTh[(0 * 256 + e) * SS + s], &g_WTl[(0 * 256 + e) * SS + s]);
            hsplit(wli, &g_WTh[(1 * 256 + e) * SS + s], &g_WTl[(1 * 256 + e) * SS + s]);
            hsplit(whr, &g_WTh[(2 * 256 + e) * SS + s], &g_WTl[(2 * 256 + e) * SS + s]);
            hsplit(whi, &g_WTh[(3 * 256 + e) * SS + s], &g_WTl[(3 * 256 + e) * SS + s]);
        } else {
            g_Wny[0 * SS + s] = wlr;
            g_Wny[1 * SS + s] = wli;
            g_Wny[2 * SS + s] = whr;
            g_Wny[3 * SS + s] = whi;
        }
    }
}

__global__ void build_bias_kernel(const float* __restrict__ lbr, const float* __restrict__ lbi,
                                  const float* __restrict__ hbr, const float* __restrict__ hbi)
{
    int n = blockIdx.x * blockDim.x + threadIdx.x;
    if (n >= NWP) return;
    int p = n >> 8, e = n & 255;
    const float* src = (p == 0) ? lbr : (p == 1) ? lbi : (p == 2) ? hbr : hbi;
    g_bias[n] = src[e];
}

__global__ void splitx_ny_kernel(const float* __restrict__ x,
                                 const float* __restrict__ lbr, const float* __restrict__ lbi,
                                 const float* __restrict__ hbr, const float* __restrict__ hbi)
{
    __shared__ float sW[4][512];
    __shared__ float sb[4];
    int t = threadIdx.x;
    for (int i = t; i < 4 * 512; i += 256) sW[i >> 9][i & 511] = g_Wny[i];
    if (t == 0) { sb[0] = lbr[256]; sb[1] = lbi[256]; sb[2] = hbr[256]; sb[3] = hbi[256]; }
    __syncthreads();
    int warp = t >> 5, lane = t & 31;
    int row = blockIdx.x * 8 + warp;
    const float* xr = x + (size_t)row * SS;
    float a0 = 0.f, a1 = 0.f, a2 = 0.f, a3 = 0.f;
#pragma unroll
    for (int i = 0; i < 4; i++) {
        int s = i * 128 + lane * 4;
        float4 v = *(const float4*)(xr + s);
        float vv[4] = {v.x, v.y, v.z, v.w};
        __half hh[4], ll[4];
#pragma unroll
        for (int j = 0; j < 4; j++) {
            hsplit(vv[j], &hh[j], &ll[j]);
            a0 += vv[j] * sW[0][s + j];
            a1 += vv[j] * sW[1][s + j];
            a2 += vv[j] * sW[2][s + j];
            a3 += vv[j] * sW[3][s + j];
        }
        size_t d = (size_t)row * SS + s;
        *(__half2*)&g_xh[d]     = __halves2half2(hh[0], hh[1]);
        *(__half2*)&g_xh[d + 2] = __halves2half2(hh[2], hh[3]);
        *(__half2*)&g_xl[d]     = __halves2half2(ll[0], ll[1]);
        *(__half2*)&g_xl[d + 2] = __halves2half2(ll[2], ll[3]);
    }
#pragma unroll
    for (int o = 16; o; o >>= 1) {
        a0 += __shfl_xor_sync(0xffffffffu, a0, o);
        a1 += __shfl_xor_sync(0xffffffffu, a1, o);
        a2 += __shfl_xor_sync(0xffffffffu, a2, o);
        a3 += __shfl_xor_sync(0xffffffffu, a3, o);
    }
    if (lane == 0) {
        g_ny[0 * MTOT + row] = fmaxf(a0 + sb[0], 0.f);
        g_ny[1 * MTOT + row] = fmaxf(a1 + sb[1], 0.f);
        g_ny[2 * MTOT + row] = fmaxf(a2 + sb[2], 0.f);
        g_ny[3 * MTOT + row] = fmaxf(a3 + sb[3], 0.f);
    }
}

__global__ void build_ct_kernel()
{
    int idx = blockIdx.x * blockDim.x + threadIdx.x;
    if (idx >= SS * XW) return;
    int s = idx / XW, k = idx - s * XW;
    float v;
    if (k < 256) {
        int e = k;
        float w = (e == 0) ? 1.f : 2.f;
        float ang = (float)((e * s) & 511) * TWO_PI_OVER_S;
        v = w * cosf(ang) * INV_SQRT_S;
    } else {
        int e = k - 256;
        if (e == 0) v = 0.f;
        else {
            float ang = (float)((e * s) & 511) * TWO_PI_OVER_S;
            v = -2.f * sinf(ang) * INV_SQRT_S;
        }
    }
    g_CT[idx] = __float2half_rn(v);
}

// fused sum + vt: reads planes 0..3 once, writes sum planes 4,5 (coalesced along e)
// and the vt transpose (via smem). Replaces sum_kernel + vt_kernel.
__global__ void post_proj_kernel()
{
    __shared__ float tr[32][33], ti[32][33];
    int b = blockIdx.z, e0 = blockIdx.y * 32, c0 = blockIdx.x * 32;
    int tx = threadIdx.x, ty = threadIdx.y;
    for (int r = ty; r < 32; r += 8) {
        size_t src = ((size_t)(b * CC + c0 + r)) * KP + (e0 + tx);
        float lr = __half2float(g_lowh[0 * PSL + src]) + __half2float(g_lowl[0 * PSL + src]);
        float li = __half2float(g_lowh[1 * PSL + src]) + __half2float(g_lowl[1 * PSL + src]);
        float hr = __half2float(g_lowh[2 * PSL + src]) + __half2float(g_lowl[2 * PSL + src]);
        float hi = __half2float(g_lowh[3 * PSL + src]) + __half2float(g_lowl[3 * PSL + src]);
        hsplit(lr + li, &g_lowh[4 * PSL + src], &g_lowl[4 * PSL + src]);
        hsplit(hr + hi, &g_lowh[5 * PSL + src], &g_lowl[5 * PSL + src]);
        tr[r][tx] = lr;
        ti[r][tx] = li;
    }
    __syncthreads();
    for (int r = ty; r < 32; r += 8) {
        int n = e0 + r, c = c0 + tx;
        float lr = tr[tx][r], li = ti[tx][r];
        size_t d0 = ((size_t)(b * 2 + 0) * 256 + n) * 1024;
        size_t d1 = ((size_t)(b * 2 + 1) * 256 + n) * 1024;
        g_vt[d0 + c]       = __float2half_rn(lr);
        g_vt[d0 + 512 + c] = __float2half_rn(-li);
        g_vt[d1 + c]       = __float2half_rn(li);
        g_vt[d1 + 512 + c] = __float2half_rn(lr);
    }
}

// ============ FUSED 3-product engine: 256x128 tile, 512 threads ============
// K-chunk 32, 4 stages x 48KB, prefetch depth 3, wait_group 2.

struct GF {
    const __half *Ah, *Al, *Bh, *Bl;
    int lda, ldb, nkc;
};

#define FSTG 49152u

__device__ __forceinline__ void gloadF(const GF& g, int kc, int stg, uint32_t base, int t)
{
    uint32_t sb = base + (uint32_t)stg * FSTG;
    int rA = t >> 1, cA2 = (t & 1) * 2;
    const __half* gAh = g.Ah + (size_t)rA * g.lda + kc * 32 + cA2 * 8;
    const __half* gAl = g.Al + (size_t)rA * g.lda + kc * 32 + cA2 * 8;
    uint32_t mA = (uint32_t)((rA >> 1) & 3);
    uint32_t sAh = sb + (uint32_t)rA * 64u;
    uint32_t sAl = sAh + 16384u;
#pragma unroll
    for (int i = 0; i < 2; i++) {
        uint32_t c = (uint32_t)(cA2 + i);
        uint32_t sw = (c ^ mA) << 4;
        cpasync16(sAh + sw, gAh + i * 8);
        cpasync16(sAl + sw, gAl + i * 8);
    }
    int rB = t >> 2, cB = t & 3;
    const __half* gBh = g.Bh + (size_t)rB * g.ldb + kc * 32 + cB * 8;
    const __half* gBl = g.Bl + (size_t)rB * g.ldb + kc * 32 + cB * 8;
    uint32_t swB = (uint32_t)((cB ^ ((rB >> 1) & 3)) << 4);
    uint32_t sBh = sb + 32768u + (uint32_t)rB * 64u;
    uint32_t sBl = sBh + 8192u;
    cpasync16(sBh + swB, gBh);
    cpasync16(sBl + swB, gBl);
    asm volatile("cp.async.commit_group;");
}

__device__ __forceinline__ void gemmF_run(const GF& g, float (&acc)[4][4][4], uint32_t base)
{
    const int t = threadIdx.x;
    const int warp = t >> 5, lane = t & 31;
    const int wr = warp >> 2, wc = warp & 3;
    const int nkc = g.nkc;

    gloadF(g, 0, 0, base, t);
    if (nkc > 1) gloadF(g, 1, 1, base, t);
    if (nkc > 2) gloadF(g, 2, 2, base, t);
    for (int ch = 0; ch < nkc; ch++) {
        wait_upto(nkc - 1 - ch);
        __syncthreads();
        if (ch + 3 < nkc) gloadF(g, ch + 3, (ch + 3) & 3, base, t);
        uint32_t sb = base + (uint32_t)(ch & 3) * FSTG;
        uint32_t sAh = sb, sAl = sb + 16384u, sBh = sb + 32768u, sBl = sb + 40960u;
#pragma unroll
        for (int s = 0; s < 2; s++) {
            uint32_t aoffv[4], boffv[2];
#pragma unroll
            for (int mt = 0; mt < 4; mt++) {
                int row = wr * 64 + mt * 16 + (lane & 15);
                uint32_t u = (uint32_t)(s * 2 + (lane >> 4));
                aoffv[mt] = (uint32_t)row * 64u + (((u ^ ((uint32_t)(row >> 1) & 3u))) << 4);
            }
#pragma unroll
            for (int ntp = 0; ntp < 2; ntp++) {
                int row = wc * 32 + ntp * 16 + (((lane >> 4) & 1) << 3) + (lane & 7);
                uint32_t u = (uint32_t)(s * 2 + ((lane >> 3) & 1));
                boffv[ntp] = (uint32_t)row * 64u + (((u ^ ((uint32_t)(row >> 1) & 3u))) << 4);
            }
            uint32_t a[4][4], bh[2][4], bl[2][4];
#pragma unroll
            for (int mt = 0; mt < 4; mt++) ldsm4(a[mt], sAh + aoffv[mt]);
#pragma unroll
            for (int ntp = 0; ntp < 2; ntp++) {
                ldsm4(bh[ntp], sBh + boffv[ntp]);
                ldsm4(bl[ntp], sBl + boffv[ntp]);
            }
#pragma unroll
            for (int mt = 0; mt < 4; mt++)
#pragma unroll
                for (int nt = 0; nt < 4; nt++)
                    mma16816b(acc[mt][nt], a[mt], bh[nt >> 1][(nt & 1) * 2],
                              bh[nt >> 1][(nt & 1) * 2 + 1]);
#pragma unroll
            for (int mt = 0; mt < 4; mt++)
#pragma unroll
                for (int nt = 0; nt < 4; nt++)
                    mma16816b(acc[mt][nt], a[mt], bl[nt >> 1][(nt & 1) * 2],
                              bl[nt >> 1][(nt & 1) * 2 + 1]);
#pragma unroll
            for (int mt = 0; mt < 4; mt++) ldsm4(a[mt], sAl + aoffv[mt]);
#pragma unroll
            for (int mt = 0; mt < 4; mt++)
#pragma unroll
                for (int nt = 0; nt < 4; nt++)
                    mma16816b(acc[mt][nt], a[mt], bh[nt >> 1][(nt & 1) * 2],
                              bh[nt >> 1][(nt & 1) * 2 + 1]);
        }
    }
    __syncthreads();
}

#define MMA_SMEMF (4 * FSTG + 128)

// ============ single-product 256x128 engine, 512 threads, 4 stages ============

struct GS {
    const __half *A, *B;
    int lda, ldb, nkc;
};

#define SSTG 49152u

__device__ __forceinline__ void gloadS(const GS& g, int kc, int stg, uint32_t base, int t)
{
    uint32_t sb = base + (uint32_t)stg * SSTG;
    int rA = t >> 1, cA = (t & 1) * 4;
    const __half* gA = g.A + (size_t)rA * g.lda + kc * 64 + cA * 8;
    uint32_t sA = sb + (uint32_t)rA * 128u;
#pragma unroll
    for (int i = 0; i < 4; i++) {
        int c = cA + i;
        uint32_t sw = (uint32_t)((c ^ (rA & 7)) << 4);
        cpasync16(sA + sw, gA + i * 8);
    }
    int rB = t >> 2, cB = (t & 3) * 2;
    const __half* gB = g.B + (size_t)rB * g.ldb + kc * 64 + cB * 8;
    uint32_t sB = sb + 32768u + (uint32_t)rB * 128u;
#pragma unroll
    for (int i = 0; i < 2; i++) {
        int c = cB + i;
        uint32_t sw = (uint32_t)((c ^ (rB & 7)) << 4);
        cpasync16(sB + sw, gB + i * 8);
    }
    asm volatile("cp.async.commit_group;");
}

__device__ __forceinline__ void gemmS_run(const GS& g, float (&acc)[4][4][4], uint32_t base)
{
    const int t = threadIdx.x;
    const int warp = t >> 5, lane = t & 31;
    const int wr = warp >> 2, wc = warp & 3;
    const int nkc = g.nkc;

    gloadS(g, 0, 0, base, t);
    if (nkc > 1) gloadS(g, 1, 1, base, t);
    if (nkc > 2) gloadS(g, 2, 2, base, t);
    for (int ch = 0; ch < nkc; ch++) {
        wait_upto(nkc - 1 - ch);
        __syncthreads();
        if (ch + 3 < nkc) gloadS(g, ch + 3, (ch + 3) & 3, base, t);
        uint32_t sb = base + (uint32_t)(ch & 3) * SSTG;
        uint32_t sA = sb, sB = sb + 32768u;
#pragma unroll
        for (int s = 0; s < 4; s++) {
            uint32_t a[4][4], b[2][4];
#pragma unroll
            for (int mt = 0; mt < 4; mt++) {
                int row = wr * 64 + mt * 16 + (lane & 15);
                int u = s * 2 + (lane >> 4);
                ldsm4(a[mt], sA + (uint32_t)row * 128u + (uint32_t)((u ^ (row & 7)) << 4));
            }
#pragma unroll
            for (int ntp = 0; ntp < 2; ntp++) {
                int row = wc * 32 + ntp * 16 + (((lane >> 4) & 1) << 3) + (lane & 7);
                int u = s * 2 + ((lane >> 3) & 1);
                ldsm4(b[ntp], sB + (uint32_t)row * 128u + (uint32_t)((u ^ (row & 7)) << 4));
            }
#pragma unroll
            for (int mt = 0; mt < 4; mt++)
#pragma unroll
                for (int nt = 0; nt < 4; nt++)
                    mma16816b(acc[mt][nt], a[mt], b[nt >> 1][(nt & 1) * 2],
                              b[nt >> 1][(nt & 1) * 2 + 1]);
        }
    }
    __syncthreads();
}

#define MMA_SMEMS (4 * SSTG + 128)

#define GEMM_PRE() \
    extern __shared__ char dynsm[]; \
    uint32_t raw = smem_u32(dynsm); \
    uint32_t base = (raw + 127u) & ~127u; \
    char* smp = dynsm + (base - raw); \
    (void)smp; \
    float acc[4][4][4]; \
    for (int i = 0; i < 4; i++) for (int j = 0; j < 4; j++) for (int q = 0; q < 4; q++) acc[i][j][q] = 0.f; \
    const int warp = threadIdx.x >> 5, lane = threadIdx.x & 31; \
    const int wr = warp >> 2, wc = warp & 3; \
    const int gr = lane >> 2, gc = lane & 3;

// ---------------- proj: relu(x@W + bias), fused 256x128 ----------------
__global__ __launch_bounds__(512, 1) void proj_mma()
{
    GEMM_PRE();
    int n0 = blockIdx.x * 128, m0 = blockIdx.y * 256;
    GF g;
    g.Ah = g_xh + (size_t)m0 * SS;   g.Al = g_xl + (size_t)m0 * SS;
    g.Bh = g_WTh + (size_t)n0 * SS;  g.Bl = g_WTl + (size_t)n0 * SS;
    g.lda = SS; g.ldb = SS; g.nkc = 16;
    gemmF_run(g, acc, base);
#pragma unroll
    for (int mt = 0; mt < 4; mt++) {
#pragma unroll
        for (int nt = 0; nt < 4; nt++) {
            int col = n0 + wc * 32 + nt * 8 + gc * 2;
            int p = col >> 8, e = col & 255;
            float b0 = g_bias[col], b1 = g_bias[col + 1];
#pragma unroll
            for (int h = 0; h < 2; h++) {
                int row = m0 + wr * 64 + mt * 16 + gr + h * 8;
                float v0 = fmaxf(acc[mt][nt][h * 2 + 0] + b0, 0.f);
                float v1 = fmaxf(acc[mt][nt][h * 2 + 1] + b1, 0.f);
                size_t d = (size_t)p * PSL + (size_t)row * KP + e;
                __half h0, l0, h1, l1;
                hsplit(v0, &h0, &l0);
                hsplit(v1, &h1, &l1);
                *(__half2*)&g_lowh[d] = __halves2half2(h0, h1);
                *(__half2*)&g_lowl[d] = __halves2half2(l0, l1);
            }
        }
    }
}

// ---------------- score: 6 Karatsuba planes, fused, symmetric-skip + rank-1 ----------------
__global__ __launch_bounds__(512, 1) void score_mma()
{
    int z = blockIdx.z;
    int b = z / 6, which = z - b * 6;
    int hi = (which >= 3) ? 1 : 0;
    int w = which - 3 * hi;
    int apn = (w == 2) ? 4 : w;
    int bpn = hi ? ((w == 2) ? 5 : w + 2) : apn;
    int m_t, n_t;
    bool dotrans = false;
    if (!hi) {
        int tid8 = blockIdx.y * 4 + blockIdx.x;
        if (tid8 >= 6) return;
        const int mts[6] = {0, 0, 0, 0, 1, 1};
        const int nts[6] = {0, 1, 2, 3, 2, 3};
        m_t = mts[tid8]; n_t = nts[tid8];
        dotrans = (tid8 == 2 || tid8 == 3);
    } else {
        m_t = blockIdx.y; n_t = blockIdx.x;
    }
    GEMM_PRE();
    __shared__ float sA256[256], sB256[128];
    int m0 = m_t * 256, n0 = n_t * 128;
    if (threadIdx.x < 256)
        sA256[threadIdx.x] = plane256(apn, b * CC + m0 + threadIdx.x);
    else if (threadIdx.x < 384)
        sB256[threadIdx.x - 256] = plane256(bpn, b * CC + n0 + threadIdx.x - 256);
    size_t aoff = (size_t)apn * PSL + (size_t)(b * CC + m0) * KP;
    size_t boff = (size_t)bpn * PSL + (size_t)(b * CC + n0) * KP;
    GF g;
    g.Ah = g_lowh + aoff;  g.Al = g_lowl + aoff;
    g.Bh = g_lowh + boff;  g.Bl = g_lowl + boff;
    g.lda = KP; g.ldb = KP; g.nkc = 8;
    gemmF_run(g, acc, base);
    float* out = g_S + (size_t)which * PS + (size_t)(b * CC) * CC;
#pragma unroll
    for (int mt = 0; mt < 4; mt++) {
#pragma unroll
        for (int nt = 0; nt < 4; nt++) {
            int cl = wc * 32 + nt * 8 + gc * 2;
            float bv0 = sB256[cl], bv1 = sB256[cl + 1];
            int col = n0 + cl;
#pragma unroll
            for (int h = 0; h < 2; h++) {
                int rl = wr * 64 + mt * 16 + gr + h * 8;
                float av = sA256[rl];
                int row = m0 + rl;
                *(float2*)&out[(size_t)row * CC + col] =
                    make_float2(acc[mt][nt][h * 2 + 0] + av * bv0,
                                acc[mt][nt][h * 2 + 1] + av * bv1);
            }
        }
    }
    if (dotrans) {
        float* T = (float*)smp;   // [128][132]
        for (int h2 = 0; h2 < 2; h2++) {
            __syncthreads();
            if ((wr >> 1) == h2) {
#pragma unroll
                for (int mt = 0; mt < 4; mt++) {
#pragma unroll
                    for (int nt = 0; nt < 4; nt++) {
                        int cl = wc * 32 + nt * 8 + gc * 2;
                        float bv0 = sB256[cl], bv1 = sB256[cl + 1];
#pragma unroll
                        for (int h = 0; h < 2; h++) {
                            int rl = wr * 64 + mt * 16 + gr + h * 8;
                            int j = rl - h2 * 128;
                            float av = sA256[rl];
                            T[cl * 132 + j]       = acc[mt][nt][h * 2 + 0] + av * bv0;
                            T[(cl + 1) * 132 + j] = acc[mt][nt][h * 2 + 1] + av * bv1;
                        }
                    }
                }
            }
            __syncthreads();
            for (int idx = threadIdx.x; idx < 128 * 32; idx += 512) {
                int c = idx >> 5, q = idx & 31;
                float4 v = *(float4*)&T[c * 132 + q * 4];
                *(float4*)&out[(size_t)(n0 + c) * CC + (h2 * 128 + q * 4)] = v;
            }
        }
    }
}

// ---------------- softmax + Karatsuba combine (vectorized I/O) ----------------
__device__ __forceinline__ void softmax16(float (&v)[16])
{
    float m = -3.4e38f;
#pragma unroll
    for (int u = 0; u < 16; u++) m = fmaxf(m, v[u]);
#pragma unroll
    for (int o = 16; o; o >>= 1) m = fmaxf(m, __shfl_xor_sync(0xffffffffu, m, o));
    float s = 0.f;
#pragma unroll
    for (int u = 0; u < 16; u++) { v[u] = expf(v[u] - m); s += v[u]; }
#pragma unroll
    for (int o = 16; o; o >>= 1) s += __shfl_xor_sync(0xffffffffu, s, o);
    float r = 1.f / s;
#pragma unroll
    for (int u = 0; u < 16; u++) v[u] *= r;
}

__global__ void softmax_kernel()
{
    int gw = (blockIdx.x * blockDim.x + threadIdx.x) >> 5;
    int lane = threadIdx.x & 31;
    size_t base = (size_t)gw * CC;
    float t1[16], t2[16], t3[16], sr[16], si[16], pr[16], pi[16];
    // c = u*64 + lane*2 (+0,+1): float2/half2 vectorized, coalesced 128B/warp
#pragma unroll
    for (int u = 0; u < 8; u++) {
        int c = u * 64 + lane * 2;
        float2 a = *(const float2*)&g_S[0 * PS + base + c];
        float2 b2 = *(const float2*)&g_S[1 * PS + base + c];
        float2 d2 = *(const float2*)&g_S[2 * PS + base + c];
        t1[2 * u] = a.x;  t1[2 * u + 1] = a.y;
        t2[2 * u] = b2.x; t2[2 * u + 1] = b2.y;
        t3[2 * u] = d2.x; t3[2 * u + 1] = d2.y;
    }
#pragma unroll
    for (int u = 0; u < 16; u++) {
        sr[u] = (t1[u] - t2[u]) * ATTN_SCALE;
        si[u] = (t3[u] - t1[u] - t2[u]) * ATTN_SCALE;
    }
    softmax16(sr);
    softmax16(si);
#pragma unroll
    for (int u = 0; u < 16; u++) { pr[u] = sr[u]; pi[u] = si[u]; }
#pragma unroll
    for (int u = 0; u < 8; u++) {
        int c = u * 64 + lane * 2;
        float2 a = *(const float2*)&g_S[3 * PS + base + c];
        float2 b2 = *(const float2*)&g_S[4 * PS + base + c];
        float2 d2 = *(const float2*)&g_S[5 * PS + base + c];
        t1[2 * u] = a.x;  t1[2 * u + 1] = a.y;
        t2[2 * u] = b2.x; t2[2 * u + 1] = b2.y;
        t3[2 * u] = d2.x; t3[2 * u + 1] = d2.y;
    }
#pragma unroll
    for (int u = 0; u < 16; u++) {
        sr[u] = (t1[u] - t2[u]) * ATTN_SCALE;
        si[u] = (t3[u] - t1[u] - t2[u]) * ATTN_SCALE;
    }
    softmax16(sr);
    softmax16(si);
    int brow = (gw >> 9) << 9;   // b * CC
    float xr = 0.f;
#pragma unroll
    for (int u = 0; u < 8; u++) {
        int c = u * 64 + lane * 2;
        float p0 = pr[2 * u] + sr[2 * u],     p1 = pr[2 * u + 1] + sr[2 * u + 1];
        float q0 = pi[2 * u] + si[2 * u],     q1 = pi[2 * u + 1] + si[2 * u + 1];
        size_t d = (size_t)gw * 1024 + c;
        *(__half2*)&g_P[d]       = __floats2half2_rn(p0, p1);
        *(__half2*)&g_P[d + 512] = __floats2half2_rn(q0, q1);
        float2 vr = *(const float2*)&g_ny[0 * MTOT + brow + c];
        float2 vi = *(const float2*)&g_ny[1 * MTOT + brow + c];
        xr += p0 * vr.x + p1 * vr.y - q0 * vi.x - q1 * vi.y;
    }
#pragma unroll
    for (int o = 16; o; o >>= 1) xr += __shfl_xor_sync(0xffffffffu, xr, o);
    if (lane == 0) g_Xny[gw] = xr;
}

// ---------------- attnv: X = P @ vt^T, 256x128 engine, K=1024 ----------------
__global__ __launch_bounds__(512, 1) void attnv_mma()
{
    GEMM_PRE();
    int z = blockIdx.z;
    int b = z >> 1, pl = z & 1;
    int n0 = blockIdx.x * 128, m0 = blockIdx.y * 256;
    GS g;
    g.A = g_P + (size_t)(b * CC + m0) * 1024;
    g.B = g_vt + ((size_t)(b * 2 + pl) * 256 + n0) * 1024;
    g.lda = 1024; g.ldb = 1024; g.nkc = 16;
    gemmS_run(g, acc, base);
#pragma unroll
    for (int mt = 0; mt < 4; mt++) {
#pragma unroll
        for (int nt = 0; nt < 4; nt++) {
            int col = n0 + wc * 32 + nt * 8 + gc * 2;
#pragma unroll
            for (int h = 0; h < 2; h++) {
                int row = m0 + wr * 64 + mt * 16 + gr + h * 8;
                size_t d = (size_t)(b * CC + row) * XW + (size_t)pl * 256 + col;
                __half2 v = __floats2half2_rn(acc[mt][nt][h * 2 + 0], acc[mt][nt][h * 2 + 1]);
                *(__half2*)&g_X[d] = v;
            }
        }
    }
}

// ---------------- irfft: out = X @ CT^T (K=512) + Nyquist rank-1 ----------------
__global__ __launch_bounds__(512, 1) void irfft_mma(float* __restrict__ out)
{
    GEMM_PRE();
    __shared__ float sXny[256];
    int n0 = blockIdx.x * 128, m0 = blockIdx.y * 256;
    if (threadIdx.x < 256) sXny[threadIdx.x] = g_Xny[m0 + threadIdx.x];
    GS g;
    g.A = g_X + (size_t)m0 * XW;
    g.B = g_CT + (size_t)n0 * XW;
    g.lda = XW; g.ldb = XW; g.nkc = 8;
    gemmS_run(g, acc, base);
#pragma unroll
    for (int mt = 0; mt < 4; mt++) {
#pragma unroll
        for (int nt = 0; nt < 4; nt++) {
            int col = n0 + wc * 32 + nt * 8 + gc * 2;
            float w0 = (col & 1) ? -INV_SQRT_S : INV_SQRT_S;
#pragma unroll
            for (int h = 0; h < 2; h++) {
                int rl = wr * 64 + mt * 16 + gr + h * 8;
                float xny = sXny[rl];
                int row = m0 + rl;
                *(float2*)&out[(size_t)row * SS + col] =
                    make_float2(acc[mt][nt][h * 2 + 0] + xny * w0,
                                acc[mt][nt][h * 2 + 1] - xny * w0);
            }
        }
    }
}

// ---------------- launch ----------------

extern "C" void kernel_launch(void* const* d_in, const int* in_sizes, int n_in,
                              void* d_out, int out_size)
{
    const float* x   = (const float*)d_in[0];
    const float* l1r = (const float*)d_in[1];
    const float* l1i = (const float*)d_in[2];
    const float* h1r = (const float*)d_in[3];
    const float* h1i = (const float*)d_in[4];
    const float* lbr = (const float*)d_in[5];
    const float* lbi = (const float*)d_in[6];
    const float* hbr = (const float*)d_in[7];
    const float* hbi = (const float*)d_in[8];
    float* out = (float*)d_out;

    cudaFuncSetAttribute(proj_mma,  cudaFuncAttributeMaxDynamicSharedMemorySize, MMA_SMEMF);
    cudaFuncSetAttribute(score_mma, cudaFuncAttributeMaxDynamicSharedMemorySize, MMA_SMEMF);
    cudaFuncSetAttribute(attnv_mma, cudaFuncAttributeMaxDynamicSharedMemorySize, MMA_SMEMS);
    cudaFuncSetAttribute(irfft_mma, cudaFuncAttributeMaxDynamicSharedMemorySize, MMA_SMEMS);

    // launch order chosen so ncu (-s 5 -c 1) profiles score_mma (index 5)
    build_w_kernel<<<512, 256>>>(l1r, l1i, h1r, h1i);                        // 0
    build_bias_kernel<<<(NWP + 255) / 256, 256>>>(lbr, lbi, hbr, hbi);       // 1
    splitx_ny_kernel<<<MTOT / 8, 256>>>(x, lbr, lbi, hbr, hbi);              // 2
    proj_mma<<<dim3(NWP / 128, MTOT / 256), 512, MMA_SMEMF>>>();             // 3 (8, 128)
    post_proj_kernel<<<dim3(CC / 32, 256 / 32, BB), dim3(32, 8)>>>();        // 4
    score_mma<<<dim3(4, 2, BB * 6), 512, MMA_SMEMF>>>();                     // 5 <- profiled
    softmax_kernel<<<MTOT / 8, 256>>>();                                     // 6
    build_ct_kernel<<<(SS * XW + 255) / 256, 256>>>();                       // 7
    attnv_mma<<<dim3(2, 2, BB * 2), 512, MMA_SMEMS>>>();                     // 8
    irfft_mma<<<dim3(4, MTOT / 256), 512, MMA_SMEMS>>>(out);                 // 9
}